// round 13
// baseline (speedup 1.0000x reference)
#include <cuda_runtime.h>
#include <cuda_bf16.h>
#include <math.h>
#include <stdint.h>

// Problem constants
#define LQ   512
#define LK   4096
#define BB   4
#define DD   512
#define DFF  2048
#define HH   8
#define HD   64
#define LKH  (LK / 2)
#define LN_EPS 1e-5f

// ------------------------- scratch (device globals) -----------------------
__device__ float  g_t  [LQ * BB * DD];
__device__ float  g_ctx[LQ * BB * DD];
__device__ float  g_x1 [LQ * BB * DD];
__device__ float  g_xn [LQ * BB * DD];
__device__ uint32_t g_qh [LQ * BB * (DD / 2)];        // Q (scaled) bf16-hi packed
__device__ uint32_t g_ql [LQ * BB * (DD / 2)];
__device__ uint32_t g_mh [LK * BB * (DD / 2)];        // LN2(memory) bf16-hi packed
__device__ uint32_t g_ml [LK * BB * (DD / 2)];
__device__ uint32_t g_kh [LK * BB * (DD / 2)];        // K bf16-hi packed along d
__device__ uint32_t g_kl [LK * BB * (DD / 2)];
__device__ uint32_t g_vth[BB * DD * LKH + 64];        // V^T bf16-hi packed along k
__device__ uint32_t g_vtl[BB * DD * LKH + 64];
__device__ uint32_t g_ff1h[LQ * BB * (DFF / 2)];      // relu(ff1) bf16-hi packed
__device__ uint32_t g_ff1l[LQ * BB * (DFF / 2)];
// pre-split weights: [n][k/2] packed
__device__ uint32_t g_wqh[DD * DD / 2],  g_wql[DD * DD / 2];
__device__ uint32_t g_wkh[DD * DD / 2],  g_wkl[DD * DD / 2];
__device__ uint32_t g_wvh[DD * DD / 2],  g_wvl[DD * DD / 2];
__device__ uint32_t g_woh[DD * DD / 2],  g_wol[DD * DD / 2];
__device__ uint32_t g_w1h[DFF * DD / 2], g_w1l[DFF * DD / 2];
__device__ uint32_t g_w2h[DD * DFF / 2], g_w2l[DD * DFF / 2];

// ------------------------- reductions ------------------------------------
__device__ __forceinline__ float warpReduceSum(float v) {
    #pragma unroll
    for (int o = 16; o > 0; o >>= 1) v += __shfl_down_sync(0xffffffffu, v, o);
    return v;
}
__device__ __forceinline__ float blockReduceSum256(float v, float* shared) {
    __syncthreads();
    int lane = threadIdx.x & 31, wid = threadIdx.x >> 5;
    v = warpReduceSum(v);
    if (lane == 0) shared[wid] = v;
    __syncthreads();
    if (wid == 0) {
        float x = (lane < 8) ? shared[lane] : 0.f;
        #pragma unroll
        for (int o = 4; o > 0; o >>= 1) x += __shfl_down_sync(0xffffffffu, x, o);
        if (lane == 0) shared[0] = x;
    }
    __syncthreads();
    return shared[0];
}

// ------------------------- LayerNorm (row length 512) ---------------------
__global__ void ln_kernel(const float* __restrict__ in,
                          const float* __restrict__ w,
                          const float* __restrict__ b,
                          float* __restrict__ out)
{
    __shared__ float red[8];
    const int r = blockIdx.x;
    const float* xp = in + (size_t)r * DD;
    float* op = out + (size_t)r * DD;
    int t = threadIdx.x;

    float x0 = xp[t], x1 = xp[t + 256];
    float s = blockReduceSum256(x0 + x1, red);
    float mu = s * (1.0f / DD);
    float d0 = x0 - mu, d1 = x1 - mu;
    float ss = blockReduceSum256(d0 * d0 + d1 * d1, red);
    float rstd = rsqrtf(ss * (1.0f / DD) + LN_EPS);
    op[t]       = d0 * rstd * w[t]       + b[t];
    op[t + 256] = d1 * rstd * w[t + 256] + b[t + 256];
}

// ------------------------- bf16 / mma / async helpers ----------------------
__device__ __forceinline__ uint32_t pk(__nv_bfloat16 lo, __nv_bfloat16 hi) {
    unsigned short a = __bfloat16_as_ushort(lo);
    unsigned short b = __bfloat16_as_ushort(hi);
    return (uint32_t)a | ((uint32_t)b << 16);
}
__device__ __forceinline__ void split2(float2 f, uint32_t& h, uint32_t& l) {
    __nv_bfloat16 h0 = __float2bfloat16(f.x), h1 = __float2bfloat16(f.y);
    __nv_bfloat16 l0 = __float2bfloat16(f.x - __bfloat162float(h0));
    __nv_bfloat16 l1 = __float2bfloat16(f.y - __bfloat162float(h1));
    h = pk(h0, h1); l = pk(l0, l1);
}
__device__ __forceinline__ void mma_bf16(float* d, const uint32_t* a, uint32_t b0, uint32_t b1) {
    asm volatile(
        "mma.sync.aligned.m16n8k16.row.col.f32.bf16.bf16.f32 "
        "{%0,%1,%2,%3}, {%4,%5,%6,%7}, {%8,%9}, {%0,%1,%2,%3};"
        : "+f"(d[0]), "+f"(d[1]), "+f"(d[2]), "+f"(d[3])
        : "r"(a[0]), "r"(a[1]), "r"(a[2]), "r"(a[3]), "r"(b0), "r"(b1));
}
__device__ __forceinline__ void ldsm4(uint32_t* r, uint32_t saddr) {
    asm volatile("ldmatrix.sync.aligned.m8n8.x4.shared.b16 {%0,%1,%2,%3}, [%4];"
        : "=r"(r[0]), "=r"(r[1]), "=r"(r[2]), "=r"(r[3]) : "r"(saddr));
}
__device__ __forceinline__ void ldsm2(uint32_t* r, uint32_t saddr) {
    asm volatile("ldmatrix.sync.aligned.m8n8.x2.shared.b16 {%0,%1}, [%2];"
        : "=r"(r[0]), "=r"(r[1]) : "r"(saddr));
}
__device__ __forceinline__ void cp_async8(uint32_t saddr, const void* gaddr) {
    asm volatile("cp.async.ca.shared.global [%0], [%1], 8;" :: "r"(saddr), "l"(gaddr));
}
__device__ __forceinline__ void cp_commit() {
    asm volatile("cp.async.commit_group;");
}
template<int N>
__device__ __forceinline__ void cp_wait() {
    asm volatile("cp.async.wait_group %0;" :: "n"(N));
}

// ------------------------- weight pre-splitting ----------------------------
__global__ void split_weights(
        const float* __restrict__ w0, const float* __restrict__ w1,
        const float* __restrict__ w2, const float* __restrict__ w3,
        const float* __restrict__ w4, const float* __restrict__ w5,
        uint32_t* __restrict__ h0, uint32_t* __restrict__ l0,
        uint32_t* __restrict__ h1, uint32_t* __restrict__ l1,
        uint32_t* __restrict__ h2, uint32_t* __restrict__ l2,
        uint32_t* __restrict__ h3, uint32_t* __restrict__ l3,
        uint32_t* __restrict__ h4, uint32_t* __restrict__ l4,
        uint32_t* __restrict__ h5, uint32_t* __restrict__ l5)
{
    const float* w; uint32_t* h; uint32_t* l; int n;
    switch (blockIdx.y) {
        case 0: w = w0; h = h0; l = l0; n = DD * DD / 2;  break;
        case 1: w = w1; h = h1; l = l1; n = DD * DD / 2;  break;
        case 2: w = w2; h = h2; l = l2; n = DD * DD / 2;  break;
        case 3: w = w3; h = h3; l = l3; n = DD * DD / 2;  break;
        case 4: w = w4; h = h4; l = l4; n = DFF * DD / 2; break;
        default: w = w5; h = h5; l = l5; n = DD * DFF / 2; break;
    }
    for (int i = blockIdx.x * 256 + threadIdx.x; i < n; i += gridDim.x * 256) {
        uint32_t hh, ll;
        split2(*(const float2*)(w + 2 * i), hh, ll);
        h[i] = hh; l[i] = ll;
    }
}

// ------------------------- LN2 + split of memory ---------------------------
__global__ void prep_mem(const float* __restrict__ in,
                         const float* __restrict__ w,
                         const float* __restrict__ b,
                         uint32_t* __restrict__ mh,
                         uint32_t* __restrict__ ml)
{
    const int row  = blockIdx.x * 8 + (threadIdx.x >> 5);
    const int lane = threadIdx.x & 31;
    const float4* p = (const float4*)(in + (size_t)row * DD);
    float4 v[4];
    float s = 0.f, s2 = 0.f;
    #pragma unroll
    for (int i = 0; i < 4; i++) {
        v[i] = p[lane + 32 * i];
        s  += v[i].x + v[i].y + v[i].z + v[i].w;
        s2 += v[i].x * v[i].x + v[i].y * v[i].y + v[i].z * v[i].z + v[i].w * v[i].w;
    }
    #pragma unroll
    for (int o = 16; o > 0; o >>= 1) {
        s  += __shfl_xor_sync(0xffffffffu, s, o);
        s2 += __shfl_xor_sync(0xffffffffu, s2, o);
    }
    float mu   = s * (1.0f / DD);
    float rstd = rsqrtf(s2 * (1.0f / DD) - mu * mu + LN_EPS);
    #pragma unroll
    for (int i = 0; i < 4; i++) {
        int idx = lane + 32 * i;
        float4 lw = ((const float4*)w)[idx];
        float4 lb = ((const float4*)b)[idx];
        float4 nv;
        nv.x = (v[i].x - mu) * rstd * lw.x + lb.x;
        nv.y = (v[i].y - mu) * rstd * lw.y + lb.y;
        nv.z = (v[i].z - mu) * rstd * lw.z + lb.z;
        nv.w = (v[i].w - mu) * rstd * lw.w + lb.w;
        uint32_t h0, l0, h1, l1;
        split2(make_float2(nv.x, nv.y), h0, l0);
        split2(make_float2(nv.z, nv.w), h1, l1);
        *(uint2*)(mh + (size_t)row * (DD / 2) + 2 * idx) = make_uint2(h0, h1);
        *(uint2*)(ml + (size_t)row * (DD / 2) + 2 * idx) = make_uint2(l0, l1);
    }
}

// ------------------------- generic GEMM (Q/O/FF1/FF2) ----------------------
// W pre-split packed [n][K/2]. APRE: A pre-split packed [r][K/2].
// MODE 0: float out (+relu/res). MODE 1: packed bf16 hi/lo out (+relu, *oscale).
#define SKS 12

template<int BM, int BN, int APRE, int MODE>
__global__ __launch_bounds__(256, 2) void gemm2(
        const float* __restrict__ A,
        const uint32_t* __restrict__ pah,
        const uint32_t* __restrict__ pal,
        const uint32_t* __restrict__ wh,
        const uint32_t* __restrict__ wl,
        const float* __restrict__ bias,
        const float* __restrict__ res,
        float* __restrict__ out,
        uint32_t* __restrict__ oh,
        uint32_t* __restrict__ ol,
        float oscale,
        int N, int K, int doRelu)
{
    constexpr int FM = BM / 32;
    constexpr int FN = BN / 32;
    constexpr int LA = BM / 64;
    constexpr int LB = BN / 64;

    extern __shared__ uint32_t usmem[];
    uint32_t* sAh = usmem;
    uint32_t* sAl = sAh + 2 * BM * SKS;
    uint32_t* sBh = sAl + 2 * BM * SKS;
    uint32_t* sBl = sBh + 2 * BN * SKS;

    const int tid  = threadIdx.x;
    const int lane = tid & 31;
    const int warp = tid >> 5;
    const int g = lane >> 2, t = lane & 3;
    const int mW = (warp & 1) * (BM / 2);
    const int nW = (warp >> 1) * (BN / 4);
    const int rowBase = blockIdx.y * BM;
    const int colBase = blockIdx.x * BN;

    const uint32_t sAh_u = (uint32_t)__cvta_generic_to_shared(sAh);
    const uint32_t sAl_u = (uint32_t)__cvta_generic_to_shared(sAl);
    const uint32_t sBh_u = (uint32_t)__cvta_generic_to_shared(sBh);
    const uint32_t sBl_u = (uint32_t)__cvta_generic_to_shared(sBl);

    const uint32_t aOff = (uint32_t)(((mW + (lane & 15)) * SKS + (lane >> 4) * 4) * 4);
    const uint32_t bOff = (uint32_t)(((nW + (lane >> 3) * 8 + (lane & 7)) * SKS) * 4);

    const int lr = tid >> 2;
    const int lc = (tid & 3) * 4;
    const int K2 = K >> 1;
    const float*    Agf = A   ? A   + (size_t)(rowBase + lr) * K + lc : nullptr;
    const uint32_t* Agh = pah ? pah + (size_t)(rowBase + lr) * K2 + (lc >> 1) : nullptr;
    const uint32_t* Agl = pal ? pal + (size_t)(rowBase + lr) * K2 + (lc >> 1) : nullptr;
    const uint32_t* Wgh = wh + (size_t)(colBase + lr) * K2 + (lc >> 1);
    const uint32_t* Wgl = wl + (size_t)(colBase + lr) * K2 + (lc >> 1);

    float acc[FM][FN][4];
    #pragma unroll
    for (int i = 0; i < FM; i++)
        #pragma unroll
        for (int j = 0; j < FN; j++)
            #pragma unroll
            for (int c = 0; c < 4; c++) acc[i][j][c] = 0.f;

    float4 raf[LA];
    uint2  rah[LA], ral[LA];
    uint2  rwh[LB], rwl[LB];

    auto loadTile = [&](int tt) {
        if (APRE) {
            #pragma unroll
            for (int i = 0; i < LA; i++) {
                rah[i] = *(const uint2*)(Agh + (size_t)i * 64 * K2 + tt * 8);
                ral[i] = *(const uint2*)(Agl + (size_t)i * 64 * K2 + tt * 8);
            }
        } else {
            #pragma unroll
            for (int i = 0; i < LA; i++)
                raf[i] = *(const float4*)(Agf + (size_t)i * 64 * K + tt * 16);
        }
        #pragma unroll
        for (int i = 0; i < LB; i++) {
            rwh[i] = *(const uint2*)(Wgh + (size_t)i * 64 * K2 + tt * 8);
            rwl[i] = *(const uint2*)(Wgl + (size_t)i * 64 * K2 + tt * 8);
        }
    };

    auto stage = [&](int buf) {
        #pragma unroll
        for (int i = 0; i < LA; i++) {
            int ofs = buf * BM * SKS + (lr + 64 * i) * SKS + (lc >> 1);
            if (APRE) {
                *(uint2*)(sAh + ofs) = rah[i];
                *(uint2*)(sAl + ofs) = ral[i];
            } else {
                float4 v = raf[i];
                uint32_t h0, l0, h1, l1;
                split2(make_float2(v.x, v.y), h0, l0);
                split2(make_float2(v.z, v.w), h1, l1);
                *(uint2*)(sAh + ofs) = make_uint2(h0, h1);
                *(uint2*)(sAl + ofs) = make_uint2(l0, l1);
            }
        }
        #pragma unroll
        for (int i = 0; i < LB; i++) {
            int ofs = buf * BN * SKS + (lr + 64 * i) * SKS + (lc >> 1);
            *(uint2*)(sBh + ofs) = rwh[i];
            *(uint2*)(sBl + ofs) = rwl[i];
        }
    };

    auto compute = [&](int buf) {
        uint32_t ah[FM][4], al[FM][4];
        uint32_t bh0[4], bh1[4], bl0[4], bl1[4];
        const uint32_t aH = sAh_u + (uint32_t)(buf * BM * SKS * 4) + aOff;
        const uint32_t aL = sAl_u + (uint32_t)(buf * BM * SKS * 4) + aOff;
        #pragma unroll
        for (int mf = 0; mf < FM; mf++) {
            ldsm4(ah[mf], aH + mf * (16 * SKS * 4));
            ldsm4(al[mf], aL + mf * (16 * SKS * 4));
        }
        const uint32_t bH = sBh_u + (uint32_t)(buf * BN * SKS * 4) + bOff;
        const uint32_t bL = sBl_u + (uint32_t)(buf * BN * SKS * 4) + bOff;
        if (FN == 4) {
            ldsm4(bh0, bH); ldsm4(bh1, bH + 16);
            ldsm4(bl0, bL); ldsm4(bl1, bL + 16);
        } else {
            ldsm2(bh0, bH); ldsm2(bh1, bH + 16);
            ldsm2(bl0, bL); ldsm2(bl1, bL + 16);
        }
        #pragma unroll
        for (int mf = 0; mf < FM; mf++)
            #pragma unroll
            for (int nf = 0; nf < FN; nf++) {
                mma_bf16(acc[mf][nf], ah[mf], bh0[nf], bh1[nf]);
                mma_bf16(acc[mf][nf], ah[mf], bl0[nf], bl1[nf]);
                mma_bf16(acc[mf][nf], al[mf], bh0[nf], bh1[nf]);
            }
    };

    loadTile(0);
    stage(0);
    __syncthreads();

    const int nT = K / 16;
    int buf = 0;
    for (int tt = 1; tt < nT; tt++) {
        loadTile(tt);
        compute(buf);
        stage(buf ^ 1);
        __syncthreads();
        buf ^= 1;
    }
    compute(buf);

    if (MODE == 0) {
        #pragma unroll
        for (int mf = 0; mf < FM; mf++) {
            int row0 = rowBase + mW + mf * 16 + g;
            #pragma unroll
            for (int nf = 0; nf < FN; nf++) {
                int col = colBase + nW + nf * 8 + 2 * t;
                float2 bb = *(const float2*)(bias + col);
                float2 v0, v1;
                v0.x = acc[mf][nf][0] + bb.x; v0.y = acc[mf][nf][1] + bb.y;
                v1.x = acc[mf][nf][2] + bb.x; v1.y = acc[mf][nf][3] + bb.y;
                if (doRelu) {
                    v0.x = fmaxf(v0.x, 0.f); v0.y = fmaxf(v0.y, 0.f);
                    v1.x = fmaxf(v1.x, 0.f); v1.y = fmaxf(v1.y, 0.f);
                }
                if (res) {
                    float2 r0 = *(const float2*)(res + (size_t)row0 * N + col);
                    float2 r1 = *(const float2*)(res + (size_t)(row0 + 8) * N + col);
                    v0.x += r0.x; v0.y += r0.y;
                    v1.x += r1.x; v1.y += r1.y;
                }
                *(float2*)(out + (size_t)row0 * N + col) = v0;
                *(float2*)(out + (size_t)(row0 + 8) * N + col) = v1;
            }
        }
    } else {
        #pragma unroll
        for (int mf = 0; mf < FM; mf++) {
            int row0 = rowBase + mW + mf * 16 + g;
            #pragma unroll
            for (int nf = 0; nf < FN; nf++) {
                int col = colBase + nW + nf * 8 + 2 * t;
                float2 bb = *(const float2*)(bias + col);
                float a0 = acc[mf][nf][0] + bb.x, a1 = acc[mf][nf][1] + bb.y;
                float a2 = acc[mf][nf][2] + bb.x, a3 = acc[mf][nf][3] + bb.y;
                if (doRelu) {
                    a0 = fmaxf(a0, 0.f); a1 = fmaxf(a1, 0.f);
                    a2 = fmaxf(a2, 0.f); a3 = fmaxf(a3, 0.f);
                }
                a0 *= oscale; a1 *= oscale; a2 *= oscale; a3 *= oscale;
                uint32_t h0, l0, h1, l1;
                split2(make_float2(a0, a1), h0, l0);
                split2(make_float2(a2, a3), h1, l1);
                size_t i0 = (size_t)row0 * (N >> 1) + (col >> 1);
                size_t i1 = (size_t)(row0 + 8) * (N >> 1) + (col >> 1);
                oh[i0] = h0; ol[i0] = l0;
                oh[i1] = h1; ol[i1] = l1;
            }
        }
    }
}

// ------------------------- merged K+V projection (3-stage cp.async) --------
// blockIdx.z = 0: K-proj (packed out). blockIdx.z = 1: V-proj (transposed out).
#define KV_STAGES 3
#define SMEM_KV (KV_STAGES * SKS * 16 * (128 + 128))   // 73728 bytes

__global__ __launch_bounds__(256, 2) void gemm_kv(
        const uint32_t* __restrict__ pah,
        const uint32_t* __restrict__ pal,
        const uint32_t* __restrict__ wkh_, const uint32_t* __restrict__ wkl_,
        const uint32_t* __restrict__ wvh_, const uint32_t* __restrict__ wvl_,
        const float* __restrict__ bk, const float* __restrict__ bv,
        uint32_t* __restrict__ koh, uint32_t* __restrict__ kol,
        uint32_t* __restrict__ voh, uint32_t* __restrict__ vol)
{
    constexpr int BM = 128, BN = 128;
    constexpr int FM = 4, FN = 4, LA = 2, LB = 2;
    const int K = DD, K2 = DD / 2, N = DD;
    const int z = blockIdx.z;

    const uint32_t* wh = z ? wvh_ : wkh_;
    const uint32_t* wl = z ? wvl_ : wkl_;
    const float*  bias = z ? bv : bk;

    extern __shared__ uint32_t usmem[];
    uint32_t* sAh = usmem;                               // [S][BM*SKS]
    uint32_t* sAl = sAh + KV_STAGES * BM * SKS;
    uint32_t* sBh = sAl + KV_STAGES * BM * SKS;
    uint32_t* sBl = sBh + KV_STAGES * BN * SKS;

    const int tid  = threadIdx.x;
    const int lane = tid & 31;
    const int warp = tid >> 5;
    const int g = lane >> 2, t = lane & 3;
    const int mW = (warp & 1) * (BM / 2);
    const int nW = (warp >> 1) * (BN / 4);
    const int rowBase = blockIdx.y * BM;
    const int colBase = blockIdx.x * BN;

    const uint32_t sAh_u = (uint32_t)__cvta_generic_to_shared(sAh);
    const uint32_t sAl_u = (uint32_t)__cvta_generic_to_shared(sAl);
    const uint32_t sBh_u = (uint32_t)__cvta_generic_to_shared(sBh);
    const uint32_t sBl_u = (uint32_t)__cvta_generic_to_shared(sBl);

    const uint32_t aOff = (uint32_t)(((mW + (lane & 15)) * SKS + (lane >> 4) * 4) * 4);
    const uint32_t bOff = (uint32_t)(((nW + (lane >> 3) * 8 + (lane & 7)) * SKS) * 4);

    const int lr = tid >> 2;
    const int lc = (tid & 3) * 4;
    const uint32_t* Agh = pah + (size_t)(rowBase + lr) * K2 + (lc >> 1);
    const uint32_t* Agl = pal + (size_t)(rowBase + lr) * K2 + (lc >> 1);
    const uint32_t* Wgh = wh + (size_t)(colBase + lr) * K2 + (lc >> 1);
    const uint32_t* Wgl = wl + (size_t)(colBase + lr) * K2 + (lc >> 1);

    float acc[FM][FN][4];
    #pragma unroll
    for (int i = 0; i < FM; i++)
        #pragma unroll
        for (int j = 0; j < FN; j++)
            #pragma unroll
            for (int c = 0; c < 4; c++) acc[i][j][c] = 0.f;

    // per-thread smem byte offsets for cp.async destinations
    const uint32_t stOffA0 = (uint32_t)(((lr)      * SKS + (lc >> 1)) * 4);
    const uint32_t stOffA1 = (uint32_t)(((lr + 64) * SKS + (lc >> 1)) * 4);

    auto stageAsync = [&](int buf, int tt) {
        uint32_t bofsA = (uint32_t)(buf * BM * SKS * 4);
        uint32_t bofsB = (uint32_t)(buf * BN * SKS * 4);
        cp_async8(sAh_u + bofsA + stOffA0, Agh + tt * 8);
        cp_async8(sAh_u + bofsA + stOffA1, Agh + (size_t)64 * K2 + tt * 8);
        cp_async8(sAl_u + bofsA + stOffA0, Agl + tt * 8);
        cp_async8(sAl_u + bofsA + stOffA1, Agl + (size_t)64 * K2 + tt * 8);
        cp_async8(sBh_u + bofsB + stOffA0, Wgh + tt * 8);
        cp_async8(sBh_u + bofsB + stOffA1, Wgh + (size_t)64 * K2 + tt * 8);
        cp_async8(sBl_u + bofsB + stOffA0, Wgl + tt * 8);
        cp_async8(sBl_u + bofsB + stOffA1, Wgl + (size_t)64 * K2 + tt * 8);
        cp_commit();
    };

    auto compute = [&](int buf) {
        uint32_t ah[FM][4], al[FM][4];
        uint32_t bh0[4], bh1[4], bl0[4], bl1[4];
        const uint32_t aH = sAh_u + (uint32_t)(buf * BM * SKS * 4) + aOff;
        const uint32_t aL = sAl_u + (uint32_t)(buf * BM * SKS * 4) + aOff;
        #pragma unroll
        for (int mf = 0; mf < FM; mf++) {
            ldsm4(ah[mf], aH + mf * (16 * SKS * 4));
            ldsm4(al[mf], aL + mf * (16 * SKS * 4));
        }
        const uint32_t bH = sBh_u + (uint32_t)(buf * BN * SKS * 4) + bOff;
        const uint32_t bL = sBl_u + (uint32_t)(buf * BN * SKS * 4) + bOff;
        ldsm4(bh0, bH); ldsm4(bh1, bH + 16);
        ldsm4(bl0, bL); ldsm4(bl1, bL + 16);
        #pragma unroll
        for (int mf = 0; mf < FM; mf++)
            #pragma unroll
            for (int nf = 0; nf < FN; nf++) {
                mma_bf16(acc[mf][nf], ah[mf], bh0[nf], bh1[nf]);
                mma_bf16(acc[mf][nf], ah[mf], bl0[nf], bl1[nf]);
                mma_bf16(acc[mf][nf], al[mf], bh0[nf], bh1[nf]);
            }
    };

    const int nT = K / 16;   // 32
    stageAsync(0, 0);
    stageAsync(1, 1);

    int buf = 0;
    for (int tt = 0; tt < nT; tt++) {
        if (tt == nT - 1) cp_wait<0>(); else cp_wait<1>();
        __syncthreads();
        if (tt + 2 < nT) {
            int nb = buf + 2; if (nb >= KV_STAGES) nb -= KV_STAGES;
            stageAsync(nb, tt + 2);
        }
        compute(buf);
        buf++; if (buf >= KV_STAGES) buf = 0;
    }

    if (z == 0) {
        // K epilogue: packed bf16 hi/lo along d
        #pragma unroll
        for (int mf = 0; mf < FM; mf++) {
            int row0 = rowBase + mW + mf * 16 + g;
            #pragma unroll
            for (int nf = 0; nf < FN; nf++) {
                int col = colBase + nW + nf * 8 + 2 * t;
                float2 bb = *(const float2*)(bias + col);
                uint32_t h0, l0, h1, l1;
                split2(make_float2(acc[mf][nf][0] + bb.x, acc[mf][nf][1] + bb.y), h0, l0);
                split2(make_float2(acc[mf][nf][2] + bb.x, acc[mf][nf][3] + bb.y), h1, l1);
                size_t i0 = (size_t)row0 * (N >> 1) + (col >> 1);
                size_t i1 = (size_t)(row0 + 8) * (N >> 1) + (col >> 1);
                koh[i0] = h0; kol[i0] = l0;
                koh[i1] = h1; kol[i1] = l1;
            }
        }
    } else {
        // V epilogue: transposed packed hi/lo via smem restage
        float* smf = (float*)usmem;     // [BM][68]
        #pragma unroll
        for (int p = 0; p < 2; p++) {
            __syncthreads();
            #pragma unroll
            for (int mf = 0; mf < FM; mf++) {
                int r0 = mW + mf * 16 + g;
                #pragma unroll
                for (int nf = 0; nf < FN; nf++) {
                    int col = nW + nf * 8 + 2 * t;
                    if ((col >> 6) == p) {
                        int ch = col & 63;
                        float2 bb = *(const float2*)(bias + colBase + col);
                        smf[r0 * 68 + ch]           = acc[mf][nf][0] + bb.x;
                        smf[r0 * 68 + ch + 1]       = acc[mf][nf][1] + bb.y;
                        smf[(r0 + 8) * 68 + ch]     = acc[mf][nf][2] + bb.x;
                        smf[(r0 + 8) * 68 + ch + 1] = acc[mf][nf][3] + bb.y;
                    }
                }
            }
            __syncthreads();
            const int bq = tid & 3;
            const int d  = tid >> 2;
            const int dg = colBase + p * 64 + d;
            uint32_t hbuf[16], lbuf[16];
            #pragma unroll
            for (int j = 0; j < 16; j++) {
                float v0 = smf[(8 * j + bq) * 68 + d];
                float v1 = smf[(8 * j + 4 + bq) * 68 + d];
                split2(make_float2(v0, v1), hbuf[j], lbuf[j]);
            }
            size_t base = ((size_t)bq * DD + dg) * LKH + (rowBase >> 3);
            #pragma unroll
            for (int i = 0; i < 4; i++) {
                *(uint4*)(voh + base + 4 * i) = make_uint4(hbuf[4*i], hbuf[4*i+1], hbuf[4*i+2], hbuf[4*i+3]);
                *(uint4*)(vol + base + 4 * i) = make_uint4(lbuf[4*i], lbuf[4*i+1], lbuf[4*i+2], lbuf[4*i+3]);
            }
        }
    }
}

#define SMEM_G128 (16 * SKS * (128 + 128))
#define SMEM_G64  (16 * SKS * (64 + 64))

// ------------------------- MMA banded attention (512 threads) --------------
// Register double-buffered K/V global loads to hide L2 latency.
#define SSW 968
#define PSTR 484
#define SMEM_ATTN ((2 * 16 * PSTR + 2 * 16 * SSW + 16 + 1024) * 4)

__device__ __forceinline__ int band_start(int qi) { return (qi >= 409) ? 3268 : qi * 8; }
__device__ __forceinline__ int band_wd(int qi)    { return (qi >= 409) ? 828  : 827; }

__global__ __launch_bounds__(512) void attn_mma(
        const uint32_t* __restrict__ qph,
        const uint32_t* __restrict__ qpl,
        const uint32_t* __restrict__ kh,
        const uint32_t* __restrict__ kl,
        const uint32_t* __restrict__ vth,
        const uint32_t* __restrict__ vtl,
        float* __restrict__ ctx,
        float* __restrict__ aw)
{
    extern __shared__ uint32_t sm[];
    uint32_t* sPh = sm;                         // [16][PSTR]
    uint32_t* sPl = sPh + 16 * PSTR;
    float*    sS  = (float*)(sPl + 16 * PSTR);  // [16][SSW]
    float*    aws = sS + 16 * SSW;              // [16][SSW]
    float*    sInv = aws + 16 * SSW;            // [16]
    float*    red  = sInv + 16;                 // [8][32][4]

    const int qi0 = blockIdx.x * 16;
    const int b   = blockIdx.y;
    const int tid = threadIdx.x;
    const int lane = tid & 31;
    const int warp = tid >> 5;
    const int g = lane >> 2, t = lane & 3;

    const uint32_t sPh_u = (uint32_t)__cvta_generic_to_shared(sPh);
    const uint32_t sPl_u = (uint32_t)__cvta_generic_to_shared(sPl);

    const int ustart = band_start(qi0);
    const int uend   = band_start(qi0 + 15) + band_wd(qi0 + 15);
    const int uW     = uend - ustart;
    const int ngroups = (uW + 7) >> 3;
    const int KPAD    = ((uW + 15) >> 4) << 4;
    const int nchunks = KPAD >> 4;

    const uint32_t pRowOff = (uint32_t)(((lane & 15) * PSTR + (lane >> 4) * 4) * 4);

    for (int h = 0; h < HH; h++) {
        // ---- Q fragments direct from packed global ----
        uint32_t qah[4][4], qal[4][4];
        {
            const uint32_t* q0h = qph + ((size_t)(qi0 + g) * BB + b) * (DD / 2) + h * 32;
            const uint32_t* q8h = qph + ((size_t)(qi0 + g + 8) * BB + b) * (DD / 2) + h * 32;
            const uint32_t* q0l = qpl + ((size_t)(qi0 + g) * BB + b) * (DD / 2) + h * 32;
            const uint32_t* q8l = qpl + ((size_t)(qi0 + g + 8) * BB + b) * (DD / 2) + h * 32;
            #pragma unroll
            for (int ks = 0; ks < 4; ks++) {
                qah[ks][0] = q0h[ks * 8 + t];
                qah[ks][1] = q8h[ks * 8 + t];
                qah[ks][2] = q0h[ks * 8 + t + 4];
                qah[ks][3] = q8h[ks * 8 + t + 4];
                qal[ks][0] = q0l[ks * 8 + t];
                qal[ks][1] = q8l[ks * 8 + t];
                qal[ks][2] = q0l[ks * 8 + t + 4];
                qal[ks][3] = q8l[ks * 8 + t + 4];
            }
        }

        // ---- scores: register double-buffered K loads ----
        {
            auto loadK = [&](int grp, uint32_t kb[4][4]) {
                int key = ustart + grp * 8 + g;
                if (key > LK - 1) key = LK - 1;
                const uint32_t* krh = kh + ((size_t)key * BB + b) * (DD / 2) + h * 32;
                const uint32_t* krl = kl + ((size_t)key * BB + b) * (DD / 2) + h * 32;
                #pragma unroll
                for (int ks = 0; ks < 4; ks++) {
                    kb[ks][0] = krh[ks * 8 + t];
                    kb[ks][1] = krh[ks * 8 + t + 4];
                    kb[ks][2] = krl[ks * 8 + t];
                    kb[ks][3] = krl[ks * 8 + t + 4];
                }
            };
            int grp = warp;
            if (grp < ngroups) {
                uint32_t cur[4][4], nxt[4][4];
                loadK(grp, cur);
                while (true) {
                    int ng = grp + 16;
                    if (ng < ngroups) loadK(ng, nxt);
                    float acc[4] = {0.f, 0.f, 0.f, 0.f};
                    #pragma unroll
                    for (int ks = 0; ks < 4; ks++) {
                        mma_bf16(acc, qah[ks], cur[ks][0], cur[ks][1]);
                        mma_bf16(acc, qah[ks], cur[ks][2], cur[ks][3]);
                        mma_bf16(acc, qal[ks], cur[ks][0], cur[ks][1]);
                    }
                    *(float2*)(sS + g * SSW + grp * 8 + 2 * t)       = make_float2(acc[0], acc[1]);
                    *(float2*)(sS + (g + 8) * SSW + grp * 8 + 2 * t) = make_float2(acc[2], acc[3]);
                    if (ng >= ngroups) break;
                    #pragma unroll
                    for (int ks = 0; ks < 4; ks++) {
                        cur[ks][0] = nxt[ks][0]; cur[ks][1] = nxt[ks][1];
                        cur[ks][2] = nxt[ks][2]; cur[ks][3] = nxt[ks][3];
                    }
                    grp = ng;
                }
            }
        }
        __syncthreads();

        // ---- softmax (1 row per warp) + aws accumulate + pad + pack ----
        {
            const int r  = warp;
            const int qi = qi0 + r;
            const int j0 = band_start(qi) - ustart;
            const int W  = band_wd(qi);
            float* srow = sS + r * SSW;

            float m = -1e30f;
            for (int i = j0 + lane; i < j0 + W; i += 32) m = fmaxf(m, srow[i]);
            #pragma unroll
            for (int o = 16; o > 0; o >>= 1) m = fmaxf(m, __shfl_xor_sync(0xffffffffu, m, o));
            float sum = 0.f;
            for (int i = j0 + lane; i < j0 + W; i += 32) {
                float e = __expf(srow[i] - m);
                srow[i] = e;
                sum += e;
            }
            #pragma unroll
            for (int o = 16; o > 0; o >>= 1) sum += __shfl_xor_sync(0xffffffffu, sum, o);
            float inv = 1.0f / sum;
            if (lane == 0) sInv[r] = inv;

            float cc = inv * 0.125f;   // 1/H
            float* arow = aws + r * SSW;
            if (h == 0) {
                for (int i = j0 + lane; i < j0 + W; i += 32) arow[i] = srow[i] * cc;
            } else {
                for (int i = j0 + lane; i < j0 + W; i += 32) arow[i] += srow[i] * cc;
            }
            for (int i = lane; i < j0; i += 32) srow[i] = 0.f;
            for (int i = j0 + W + lane; i < KPAD; i += 32) srow[i] = 0.f;
            __syncwarp();

            uint32_t* prow = sPh + r * PSTR;
            uint32_t* lrow = sPl + r * PSTR;
            const int npair = KPAD >> 1;
            for (int p = lane; p < npair; p += 32) {
                uint32_t ph, pl;
                split2(*(const float2*)(srow + 2 * p), ph, pl);
                prow[p] = ph;
                lrow[p] = pl;
            }
        }
        __syncthreads();

        // ---- context: register double-buffered V loads ----
        {
            const int dimBase = h * 64 + (warp & 7) * 8;
            const int kHalf = warp >> 3;
            float cacc[4] = {0.f, 0.f, 0.f, 0.f};
            const uint32_t* vhc = vth + ((size_t)b * DD + dimBase + g) * LKH;
            const uint32_t* vlc = vtl + ((size_t)b * DD + dimBase + g) * LKH;
            const int kbase = ustart >> 1;

            int ck = kHalf;
            if (ck < nchunks) {
                uint32_t vcur[4], vnxt[4];
                {
                    int kp2 = kbase + ck * 8 + t;
                    vcur[0] = vhc[kp2]; vcur[1] = vhc[kp2 + 4];
                    vcur[2] = vlc[kp2]; vcur[3] = vlc[kp2 + 4];
                }
                while (true) {
                    int nc = ck + 2;
                    if (nc < nchunks) {
                        int kp2 = kbase + nc * 8 + t;
                        vnxt[0] = vhc[kp2]; vnxt[1] = vhc[kp2 + 4];
                        vnxt[2] = vlc[kp2]; vnxt[3] = vlc[kp2 + 4];
                    }
                    uint32_t pa[4], pl[4];
                    uint32_t ko = (uint32_t)((ck * 8) * 4);
                    ldsm4(pa, sPh_u + pRowOff + ko);
                    ldsm4(pl, sPl_u + pRowOff + ko);
                    mma_bf16(cacc, pa, vcur[0], vcur[1]);
                    mma_bf16(cacc, pa, vcur[2], vcur[3]);
                    mma_bf16(cacc, pl, vcur[0], vcur[1]);
                    if (nc >= nchunks) break;
                    vcur[0] = vnxt[0]; vcur[1] = vnxt[1];
                    vcur[2] = vnxt[2]; vcur[3] = vnxt[3];
                    ck = nc;
                }
            }
            if (warp >= 8) {
                float* rp = red + (warp - 8) * 128 + lane * 4;
                rp[0] = cacc[0]; rp[1] = cacc[1]; rp[2] = cacc[2]; rp[3] = cacc[3];
            }
            __syncthreads();
            if (warp < 8) {
                const float* rp = red + warp * 128 + lane * 4;
                cacc[0] += rp[0]; cacc[1] += rp[1]; cacc[2] += rp[2]; cacc[3] += rp[3];
                float inv0 = sInv[g];
                float inv1 = sInv[g + 8];
                *(float2*)(ctx + ((size_t)(qi0 + g) * BB + b) * DD + dimBase + 2 * t) =
                    make_float2(cacc[0] * inv0, cacc[1] * inv0);
                *(float2*)(ctx + ((size_t)(qi0 + g + 8) * BB + b) * DD + dimBase + 2 * t) =
                    make_float2(cacc[2] * inv1, cacc[3] * inv1);
            }
        }
    }
    __syncthreads();

    // ---- final attn_weights write (zeros outside band) ----
    for (int i = tid; i < 16 * 1024; i += 512) {
        int r  = i >> 10;
        int c  = (i & 1023) << 2;
        int qi = qi0 + r;
        int s0 = band_start(qi);
        int W  = band_wd(qi);
        const float* arow = aws + r * SSW;
        float4 o;
        {
            int j = c + 0, jj = j - s0;
            o.x = (jj >= 0 && jj < W) ? arow[j - ustart] : 0.f;
            j = c + 1; jj = j - s0;
            o.y = (jj >= 0 && jj < W) ? arow[j - ustart] : 0.f;
            j = c + 2; jj = j - s0;
            o.z = (jj >= 0 && jj < W) ? arow[j - ustart] : 0.f;
            j = c + 3; jj = j - s0;
            o.w = (jj >= 0 && jj < W) ? arow[j - ustart] : 0.f;
        }
        *(float4*)(aw + ((size_t)b * LQ + qi) * LK + c) = o;
    }
}

// ------------------------- launch -----------------------------------------
extern "C" void kernel_launch(void* const* d_in, const int* in_sizes, int n_in,
                              void* d_out, int out_size)
{
    const float* tgt    = (const float*)d_in[0];
    const float* memory = (const float*)d_in[1];
    const float* Wq = (const float*)d_in[2];  const float* bq = (const float*)d_in[3];
    const float* Wk = (const float*)d_in[4];  const float* bk = (const float*)d_in[5];
    const float* Wv = (const float*)d_in[6];  const float* bv = (const float*)d_in[7];
    const float* Wo = (const float*)d_in[8];  const float* bo = (const float*)d_in[9];
    const float* W1 = (const float*)d_in[10]; const float* b1 = (const float*)d_in[11];
    const float* W2 = (const float*)d_in[12]; const float* b2 = (const float*)d_in[13];
    const float* ln1w = (const float*)d_in[14]; const float* ln1b = (const float*)d_in[15];
    const float* ln2w = (const float*)d_in[16]; const float* ln2b = (const float*)d_in[17];
    const float* ln3w = (const float*)d_in[18]; const float* ln3b = (const float*)d_in[19];
    const float* ln4w = (const float*)d_in[20]; const float* ln4b = (const float*)d_in[21];

    float* out    = (float*)d_out;
    float* out_x  = out;
    float* out_aw = out + (size_t)LQ * BB * DD;

    float *t_, *ctx_, *x1_, *xn_;
    uint32_t *qh_, *ql_, *mh_, *ml_, *kh_, *kl_, *vth_, *vtl_, *ff1h_, *ff1l_;
    uint32_t *wqh_, *wql_, *wkh_, *wkl_, *wvh_, *wvl_, *woh_, *wol_, *w1h_, *w1l_, *w2h_, *w2l_;
    cudaGetSymbolAddress((void**)&t_,    g_t);
    cudaGetSymbolAddress((void**)&ctx_,  g_ctx);
    cudaGetSymbolAddress((void**)&x1_,   g_x1);
    cudaGetSymbolAddress((void**)&xn_,   g_xn);
    cudaGetSymbolAddress((void**)&qh_,   g_qh);
    cudaGetSymbolAddress((void**)&ql_,   g_ql);
    cudaGetSymbolAddress((void**)&mh_,   g_mh);
    cudaGetSymbolAddress((void**)&ml_,   g_ml);
    cudaGetSymbolAddress((void**)&kh_,   g_kh);
    cudaGetSymbolAddress((void**)&kl_,   g_kl);
    cudaGetSymbolAddress((void**)&vth_,  g_vth);
    cudaGetSymbolAddress((void**)&vtl_,  g_vtl);
    cudaGetSymbolAddress((void**)&ff1h_, g_ff1h);
    cudaGetSymbolAddress((void**)&ff1l_, g_ff1l);
    cudaGetSymbolAddress((void**)&wqh_,  g_wqh); cudaGetSymbolAddress((void**)&wql_, g_wql);
    cudaGetSymbolAddress((void**)&wkh_,  g_wkh); cudaGetSymbolAddress((void**)&wkl_, g_wkl);
    cudaGetSymbolAddress((void**)&wvh_,  g_wvh); cudaGetSymbolAddress((void**)&wvl_, g_wvl);
    cudaGetSymbolAddress((void**)&woh_,  g_woh); cudaGetSymbolAddress((void**)&wol_, g_wol);
    cudaGetSymbolAddress((void**)&w1h_,  g_w1h); cudaGetSymbolAddress((void**)&w1l_, g_w1l);
    cudaGetSymbolAddress((void**)&w2h_,  g_w2h); cudaGetSymbolAddress((void**)&w2l_, g_w2l);

    cudaFuncSetAttribute(attn_mma, cudaFuncAttributeMaxDynamicSharedMemorySize, SMEM_ATTN);
    cudaFuncSetAttribute(gemm_kv, cudaFuncAttributeMaxDynamicSharedMemorySize, SMEM_KV);
    cudaFuncSetAttribute(gemm2<128,128,0,1>, cudaFuncAttributeMaxDynamicSharedMemorySize, SMEM_G128);
    cudaFuncSetAttribute(gemm2<64,64,0,0>,   cudaFuncAttributeMaxDynamicSharedMemorySize, SMEM_G64);
    cudaFuncSetAttribute(gemm2<64,64,0,1>,   cudaFuncAttributeMaxDynamicSharedMemorySize, SMEM_G64);
    cudaFuncSetAttribute(gemm2<64,64,1,0>,   cudaFuncAttributeMaxDynamicSharedMemorySize, SMEM_G64);

    // weight pre-split + LN2-normalized memory pre-split + LN1
    split_weights<<<dim3(1024, 6), 256>>>(
        Wq, Wk, Wv, Wo, W1, W2,
        wqh_, wql_, wkh_, wkl_, wvh_, wvl_, woh_, wol_, w1h_, w1l_, w2h_, w2l_);
    prep_mem<<<(LK * BB) / 8, 256>>>(memory, ln2w, ln2b, mh_, ml_);
    ln_kernel<<<LQ * BB, 256>>>(tgt, ln1w, ln1b, t_);

    // Q projection: packed, scaled by 1/8 for attention
    gemm2<64,64,0,1><<<dim3(DD / 64, (LQ * BB) / 64), 256, SMEM_G64>>>(
        t_, nullptr, nullptr, wqh_, wql_, bq, nullptr, nullptr, qh_, ql_, 0.125f, DD, DD, 0);

    // merged K + V projections (3-stage cp.async pipeline)
    gemm_kv<<<dim3(DD / 128, (LK * BB) / 128, 2), 256, SMEM_KV>>>(
        mh_, ml_, wkh_, wkl_, wvh_, wvl_, bk, bv, kh_, kl_, vth_, vtl_);

    // MMA banded attention (512 threads)
    attn_mma<<<dim3(LQ / 16, BB), 512, SMEM_ATTN>>>(qh_, ql_, kh_, kl_, vth_, vtl_, ctx_, out_aw);

    // output projection + residual, LN3
    gemm2<64,64,0,0><<<dim3(DD / 64, (LQ * BB) / 64), 256, SMEM_G64>>>(
        ctx_, nullptr, nullptr, woh_, wol_, bo, t_, x1_, nullptr, nullptr, 1.0f, DD, DD, 0);
    ln_kernel<<<LQ * BB, 256>>>(x1_, ln3w, ln3b, xn_);

    // FFN: FF1 writes packed relu output; FF2 consumes packed A
    gemm2<128,128,0,1><<<dim3(DFF / 128, (LQ * BB) / 128), 256, SMEM_G128>>>(
        xn_, nullptr, nullptr, w1h_, w1l_, b1, nullptr, nullptr, ff1h_, ff1l_, 1.0f, DFF, DD, 1);
    gemm2<64,64,1,0><<<dim3(DD / 64, (LQ * BB) / 64), 256, SMEM_G64>>>(
        nullptr, ff1h_, ff1l_, w2h_, w2l_, b2, xn_, x1_, nullptr, nullptr, 1.0f, DD, DFF, 0);

    // LN4 -> output x
    ln_kernel<<<LQ * BB, 256>>>(x1_, ln4w, ln4b, out_x);
}

// round 14
// speedup vs baseline: 1.6875x; 1.6875x over previous
#include <cuda_runtime.h>
#include <cuda_bf16.h>
#include <math.h>
#include <stdint.h>

// Problem constants
#define LQ   512
#define LK   4096
#define BB   4
#define DD   512
#define DFF  2048
#define HH   8
#define HD   64
#define LKH  (LK / 2)
#define LN_EPS 1e-5f

// ------------------------- scratch (device globals) -----------------------
__device__ float  g_t  [LQ * BB * DD];
__device__ float  g_ctx[LQ * BB * DD];
__device__ float  g_x1 [LQ * BB * DD];
__device__ float  g_xn [LQ * BB * DD];
__device__ uint32_t g_qh [LQ * BB * (DD / 2)];        // Q (scaled) bf16-hi packed
__device__ uint32_t g_ql [LQ * BB * (DD / 2)];
__device__ uint32_t g_mh [LK * BB * (DD / 2)];        // LN2(memory) bf16-hi packed
__device__ uint32_t g_ml [LK * BB * (DD / 2)];
__device__ uint32_t g_kh [LK * BB * (DD / 2)];        // K bf16-hi packed along d
__device__ uint32_t g_kl [LK * BB * (DD / 2)];
__device__ uint32_t g_vth[BB * DD * LKH + 64];        // V^T bf16-hi packed along k
__device__ uint32_t g_vtl[BB * DD * LKH + 64];
__device__ uint32_t g_ff1h[LQ * BB * (DFF / 2)];      // relu(ff1) bf16-hi packed
__device__ uint32_t g_ff1l[LQ * BB * (DFF / 2)];
// pre-split weights: [n][k/2] packed
__device__ uint32_t g_wqh[DD * DD / 2],  g_wql[DD * DD / 2];
__device__ uint32_t g_wkh[DD * DD / 2],  g_wkl[DD * DD / 2];
__device__ uint32_t g_wvh[DD * DD / 2],  g_wvl[DD * DD / 2];
__device__ uint32_t g_woh[DD * DD / 2],  g_wol[DD * DD / 2];
__device__ uint32_t g_w1h[DFF * DD / 2], g_w1l[DFF * DD / 2];
__device__ uint32_t g_w2h[DD * DFF / 2], g_w2l[DD * DFF / 2];

// ------------------------- reductions ------------------------------------
__device__ __forceinline__ float warpReduceSum(float v) {
    #pragma unroll
    for (int o = 16; o > 0; o >>= 1) v += __shfl_down_sync(0xffffffffu, v, o);
    return v;
}
__device__ __forceinline__ float blockReduceSum256(float v, float* shared) {
    __syncthreads();
    int lane = threadIdx.x & 31, wid = threadIdx.x >> 5;
    v = warpReduceSum(v);
    if (lane == 0) shared[wid] = v;
    __syncthreads();
    if (wid == 0) {
        float x = (lane < 8) ? shared[lane] : 0.f;
        #pragma unroll
        for (int o = 4; o > 0; o >>= 1) x += __shfl_down_sync(0xffffffffu, x, o);
        if (lane == 0) shared[0] = x;
    }
    __syncthreads();
    return shared[0];
}

// ------------------------- LayerNorm (row length 512) ---------------------
__global__ void ln_kernel(const float* __restrict__ in,
                          const float* __restrict__ w,
                          const float* __restrict__ b,
                          float* __restrict__ out)
{
    __shared__ float red[8];
    const int r = blockIdx.x;
    const float* xp = in + (size_t)r * DD;
    float* op = out + (size_t)r * DD;
    int t = threadIdx.x;

    float x0 = xp[t], x1 = xp[t + 256];
    float s = blockReduceSum256(x0 + x1, red);
    float mu = s * (1.0f / DD);
    float d0 = x0 - mu, d1 = x1 - mu;
    float ss = blockReduceSum256(d0 * d0 + d1 * d1, red);
    float rstd = rsqrtf(ss * (1.0f / DD) + LN_EPS);
    op[t]       = d0 * rstd * w[t]       + b[t];
    op[t + 256] = d1 * rstd * w[t + 256] + b[t + 256];
}

// ------------------------- bf16 / mma helpers ------------------------------
__device__ __forceinline__ uint32_t pk(__nv_bfloat16 lo, __nv_bfloat16 hi) {
    unsigned short a = __bfloat16_as_ushort(lo);
    unsigned short b = __bfloat16_as_ushort(hi);
    return (uint32_t)a | ((uint32_t)b << 16);
}
__device__ __forceinline__ void split2(float2 f, uint32_t& h, uint32_t& l) {
    __nv_bfloat16 h0 = __float2bfloat16(f.x), h1 = __float2bfloat16(f.y);
    __nv_bfloat16 l0 = __float2bfloat16(f.x - __bfloat162float(h0));
    __nv_bfloat16 l1 = __float2bfloat16(f.y - __bfloat162float(h1));
    h = pk(h0, h1); l = pk(l0, l1);
}
__device__ __forceinline__ void mma_bf16(float* d, const uint32_t* a, uint32_t b0, uint32_t b1) {
    asm volatile(
        "mma.sync.aligned.m16n8k16.row.col.f32.bf16.bf16.f32 "
        "{%0,%1,%2,%3}, {%4,%5,%6,%7}, {%8,%9}, {%0,%1,%2,%3};"
        : "+f"(d[0]), "+f"(d[1]), "+f"(d[2]), "+f"(d[3])
        : "r"(a[0]), "r"(a[1]), "r"(a[2]), "r"(a[3]), "r"(b0), "r"(b1));
}
__device__ __forceinline__ void ldsm4(uint32_t* r, uint32_t saddr) {
    asm volatile("ldmatrix.sync.aligned.m8n8.x4.shared.b16 {%0,%1,%2,%3}, [%4];"
        : "=r"(r[0]), "=r"(r[1]), "=r"(r[2]), "=r"(r[3]) : "r"(saddr));
}
__device__ __forceinline__ void ldsm2(uint32_t* r, uint32_t saddr) {
    asm volatile("ldmatrix.sync.aligned.m8n8.x2.shared.b16 {%0,%1}, [%2];"
        : "=r"(r[0]), "=r"(r[1]) : "r"(saddr));
}

// ------------------------- weight pre-splitting ----------------------------
__global__ void split_weights(
        const float* __restrict__ w0, const float* __restrict__ w1,
        const float* __restrict__ w2, const float* __restrict__ w3,
        const float* __restrict__ w4, const float* __restrict__ w5,
        uint32_t* __restrict__ h0, uint32_t* __restrict__ l0,
        uint32_t* __restrict__ h1, uint32_t* __restrict__ l1,
        uint32_t* __restrict__ h2, uint32_t* __restrict__ l2,
        uint32_t* __restrict__ h3, uint32_t* __restrict__ l3,
        uint32_t* __restrict__ h4, uint32_t* __restrict__ l4,
        uint32_t* __restrict__ h5, uint32_t* __restrict__ l5)
{
    const float* w; uint32_t* h; uint32_t* l; int n;
    switch (blockIdx.y) {
        case 0: w = w0; h = h0; l = l0; n = DD * DD / 2;  break;
        case 1: w = w1; h = h1; l = l1; n = DD * DD / 2;  break;
        case 2: w = w2; h = h2; l = l2; n = DD * DD / 2;  break;
        case 3: w = w3; h = h3; l = l3; n = DD * DD / 2;  break;
        case 4: w = w4; h = h4; l = l4; n = DFF * DD / 2; break;
        default: w = w5; h = h5; l = l5; n = DD * DFF / 2; break;
    }
    for (int i = blockIdx.x * 256 + threadIdx.x; i < n; i += gridDim.x * 256) {
        uint32_t hh, ll;
        split2(*(const float2*)(w + 2 * i), hh, ll);
        h[i] = hh; l[i] = ll;
    }
}

// ------------------------- LN2 + split of memory ---------------------------
__global__ void prep_mem(const float* __restrict__ in,
                         const float* __restrict__ w,
                         const float* __restrict__ b,
                         uint32_t* __restrict__ mh,
                         uint32_t* __restrict__ ml)
{
    const int row  = blockIdx.x * 8 + (threadIdx.x >> 5);
    const int lane = threadIdx.x & 31;
    const float4* p = (const float4*)(in + (size_t)row * DD);
    float4 v[4];
    float s = 0.f, s2 = 0.f;
    #pragma unroll
    for (int i = 0; i < 4; i++) {
        v[i] = p[lane + 32 * i];
        s  += v[i].x + v[i].y + v[i].z + v[i].w;
        s2 += v[i].x * v[i].x + v[i].y * v[i].y + v[i].z * v[i].z + v[i].w * v[i].w;
    }
    #pragma unroll
    for (int o = 16; o > 0; o >>= 1) {
        s  += __shfl_xor_sync(0xffffffffu, s, o);
        s2 += __shfl_xor_sync(0xffffffffu, s2, o);
    }
    float mu   = s * (1.0f / DD);
    float rstd = rsqrtf(s2 * (1.0f / DD) - mu * mu + LN_EPS);
    #pragma unroll
    for (int i = 0; i < 4; i++) {
        int idx = lane + 32 * i;
        float4 lw = ((const float4*)w)[idx];
        float4 lb = ((const float4*)b)[idx];
        float4 nv;
        nv.x = (v[i].x - mu) * rstd * lw.x + lb.x;
        nv.y = (v[i].y - mu) * rstd * lw.y + lb.y;
        nv.z = (v[i].z - mu) * rstd * lw.z + lb.z;
        nv.w = (v[i].w - mu) * rstd * lw.w + lb.w;
        uint32_t h0, l0, h1, l1;
        split2(make_float2(nv.x, nv.y), h0, l0);
        split2(make_float2(nv.z, nv.w), h1, l1);
        *(uint2*)(mh + (size_t)row * (DD / 2) + 2 * idx) = make_uint2(h0, h1);
        *(uint2*)(ml + (size_t)row * (DD / 2) + 2 * idx) = make_uint2(l0, l1);
    }
}

// ------------------------- generic GEMM (Q/O/FF1/FF2) ----------------------
// W pre-split packed [n][K/2]. APRE: A pre-split packed [r][K/2].
// MODE 0: float out (+relu/res). MODE 1: packed bf16 hi/lo out (+relu, *oscale).
#define SKS 12

template<int BM, int BN, int APRE, int MODE>
__global__ __launch_bounds__(256, (BM == 64) ? 3 : 2) void gemm2(
        const float* __restrict__ A,
        const uint32_t* __restrict__ pah,
        const uint32_t* __restrict__ pal,
        const uint32_t* __restrict__ wh,
        const uint32_t* __restrict__ wl,
        const float* __restrict__ bias,
        const float* __restrict__ res,
        float* __restrict__ out,
        uint32_t* __restrict__ oh,
        uint32_t* __restrict__ ol,
        float oscale,
        int N, int K, int doRelu)
{
    constexpr int FM = BM / 32;
    constexpr int FN = BN / 32;
    constexpr int LA = BM / 64;
    constexpr int LB = BN / 64;

    extern __shared__ uint32_t usmem[];
    uint32_t* sAh = usmem;
    uint32_t* sAl = sAh + 2 * BM * SKS;
    uint32_t* sBh = sAl + 2 * BM * SKS;
    uint32_t* sBl = sBh + 2 * BN * SKS;

    const int tid  = threadIdx.x;
    const int lane = tid & 31;
    const int warp = tid >> 5;
    const int g = lane >> 2, t = lane & 3;
    const int mW = (warp & 1) * (BM / 2);
    const int nW = (warp >> 1) * (BN / 4);
    const int rowBase = blockIdx.y * BM;
    const int colBase = blockIdx.x * BN;

    const uint32_t sAh_u = (uint32_t)__cvta_generic_to_shared(sAh);
    const uint32_t sAl_u = (uint32_t)__cvta_generic_to_shared(sAl);
    const uint32_t sBh_u = (uint32_t)__cvta_generic_to_shared(sBh);
    const uint32_t sBl_u = (uint32_t)__cvta_generic_to_shared(sBl);

    const uint32_t aOff = (uint32_t)(((mW + (lane & 15)) * SKS + (lane >> 4) * 4) * 4);
    const uint32_t bOff = (uint32_t)(((nW + (lane >> 3) * 8 + (lane & 7)) * SKS) * 4);

    const int lr = tid >> 2;
    const int lc = (tid & 3) * 4;
    const int K2 = K >> 1;
    const float*    Agf = A   ? A   + (size_t)(rowBase + lr) * K + lc : nullptr;
    const uint32_t* Agh = pah ? pah + (size_t)(rowBase + lr) * K2 + (lc >> 1) : nullptr;
    const uint32_t* Agl = pal ? pal + (size_t)(rowBase + lr) * K2 + (lc >> 1) : nullptr;
    const uint32_t* Wgh = wh + (size_t)(colBase + lr) * K2 + (lc >> 1);
    const uint32_t* Wgl = wl + (size_t)(colBase + lr) * K2 + (lc >> 1);

    float acc[FM][FN][4];
    #pragma unroll
    for (int i = 0; i < FM; i++)
        #pragma unroll
        for (int j = 0; j < FN; j++)
            #pragma unroll
            for (int c = 0; c < 4; c++) acc[i][j][c] = 0.f;

    float4 raf[LA];
    uint2  rah[LA], ral[LA];
    uint2  rwh[LB], rwl[LB];

    auto loadTile = [&](int tt) {
        if (APRE) {
            #pragma unroll
            for (int i = 0; i < LA; i++) {
                rah[i] = *(const uint2*)(Agh + (size_t)i * 64 * K2 + tt * 8);
                ral[i] = *(const uint2*)(Agl + (size_t)i * 64 * K2 + tt * 8);
            }
        } else {
            #pragma unroll
            for (int i = 0; i < LA; i++)
                raf[i] = *(const float4*)(Agf + (size_t)i * 64 * K + tt * 16);
        }
        #pragma unroll
        for (int i = 0; i < LB; i++) {
            rwh[i] = *(const uint2*)(Wgh + (size_t)i * 64 * K2 + tt * 8);
            rwl[i] = *(const uint2*)(Wgl + (size_t)i * 64 * K2 + tt * 8);
        }
    };

    auto stage = [&](int buf) {
        #pragma unroll
        for (int i = 0; i < LA; i++) {
            int ofs = buf * BM * SKS + (lr + 64 * i) * SKS + (lc >> 1);
            if (APRE) {
                *(uint2*)(sAh + ofs) = rah[i];
                *(uint2*)(sAl + ofs) = ral[i];
            } else {
                float4 v = raf[i];
                uint32_t h0, l0, h1, l1;
                split2(make_float2(v.x, v.y), h0, l0);
                split2(make_float2(v.z, v.w), h1, l1);
                *(uint2*)(sAh + ofs) = make_uint2(h0, h1);
                *(uint2*)(sAl + ofs) = make_uint2(l0, l1);
            }
        }
        #pragma unroll
        for (int i = 0; i < LB; i++) {
            int ofs = buf * BN * SKS + (lr + 64 * i) * SKS + (lc >> 1);
            *(uint2*)(sBh + ofs) = rwh[i];
            *(uint2*)(sBl + ofs) = rwl[i];
        }
    };

    auto compute = [&](int buf) {
        uint32_t ah[FM][4], al[FM][4];
        uint32_t bh0[4], bh1[4], bl0[4], bl1[4];
        const uint32_t aH = sAh_u + (uint32_t)(buf * BM * SKS * 4) + aOff;
        const uint32_t aL = sAl_u + (uint32_t)(buf * BM * SKS * 4) + aOff;
        #pragma unroll
        for (int mf = 0; mf < FM; mf++) {
            ldsm4(ah[mf], aH + mf * (16 * SKS * 4));
            ldsm4(al[mf], aL + mf * (16 * SKS * 4));
        }
        const uint32_t bH = sBh_u + (uint32_t)(buf * BN * SKS * 4) + bOff;
        const uint32_t bL = sBl_u + (uint32_t)(buf * BN * SKS * 4) + bOff;
        if (FN == 4) {
            ldsm4(bh0, bH); ldsm4(bh1, bH + 16);
            ldsm4(bl0, bL); ldsm4(bl1, bL + 16);
        } else {
            ldsm2(bh0, bH); ldsm2(bh1, bH + 16);
            ldsm2(bl0, bL); ldsm2(bl1, bL + 16);
        }
        #pragma unroll
        for (int mf = 0; mf < FM; mf++)
            #pragma unroll
            for (int nf = 0; nf < FN; nf++) {
                mma_bf16(acc[mf][nf], ah[mf], bh0[nf], bh1[nf]);
                mma_bf16(acc[mf][nf], ah[mf], bl0[nf], bl1[nf]);
                mma_bf16(acc[mf][nf], al[mf], bh0[nf], bh1[nf]);
            }
    };

    loadTile(0);
    stage(0);
    __syncthreads();

    const int nT = K / 16;
    int buf = 0;
    for (int tt = 1; tt < nT; tt++) {
        loadTile(tt);
        compute(buf);
        stage(buf ^ 1);
        __syncthreads();
        buf ^= 1;
    }
    compute(buf);

    if (MODE == 0) {
        #pragma unroll
        for (int mf = 0; mf < FM; mf++) {
            int row0 = rowBase + mW + mf * 16 + g;
            #pragma unroll
            for (int nf = 0; nf < FN; nf++) {
                int col = colBase + nW + nf * 8 + 2 * t;
                float2 bb = *(const float2*)(bias + col);
                float2 v0, v1;
                v0.x = acc[mf][nf][0] + bb.x; v0.y = acc[mf][nf][1] + bb.y;
                v1.x = acc[mf][nf][2] + bb.x; v1.y = acc[mf][nf][3] + bb.y;
                if (doRelu) {
                    v0.x = fmaxf(v0.x, 0.f); v0.y = fmaxf(v0.y, 0.f);
                    v1.x = fmaxf(v1.x, 0.f); v1.y = fmaxf(v1.y, 0.f);
                }
                if (res) {
                    float2 r0 = *(const float2*)(res + (size_t)row0 * N + col);
                    float2 r1 = *(const float2*)(res + (size_t)(row0 + 8) * N + col);
                    v0.x += r0.x; v0.y += r0.y;
                    v1.x += r1.x; v1.y += r1.y;
                }
                *(float2*)(out + (size_t)row0 * N + col) = v0;
                *(float2*)(out + (size_t)(row0 + 8) * N + col) = v1;
            }
        }
    } else {
        #pragma unroll
        for (int mf = 0; mf < FM; mf++) {
            int row0 = rowBase + mW + mf * 16 + g;
            #pragma unroll
            for (int nf = 0; nf < FN; nf++) {
                int col = colBase + nW + nf * 8 + 2 * t;
                float2 bb = *(const float2*)(bias + col);
                float a0 = acc[mf][nf][0] + bb.x, a1 = acc[mf][nf][1] + bb.y;
                float a2 = acc[mf][nf][2] + bb.x, a3 = acc[mf][nf][3] + bb.y;
                if (doRelu) {
                    a0 = fmaxf(a0, 0.f); a1 = fmaxf(a1, 0.f);
                    a2 = fmaxf(a2, 0.f); a3 = fmaxf(a3, 0.f);
                }
                a0 *= oscale; a1 *= oscale; a2 *= oscale; a3 *= oscale;
                uint32_t h0, l0, h1, l1;
                split2(make_float2(a0, a1), h0, l0);
                split2(make_float2(a2, a3), h1, l1);
                size_t i0 = (size_t)row0 * (N >> 1) + (col >> 1);
                size_t i1 = (size_t)(row0 + 8) * (N >> 1) + (col >> 1);
                oh[i0] = h0; ol[i0] = l0;
                oh[i1] = h1; ol[i1] = l1;
            }
        }
    }
}

// ------------------------- merged K+V projection (R12 proven version) ------
// blockIdx.z = 0: K-proj (packed out). blockIdx.z = 1: V-proj (transposed out).
__global__ __launch_bounds__(256, 2) void gemm_kv(
        const uint32_t* __restrict__ pah,
        const uint32_t* __restrict__ pal,
        const uint32_t* __restrict__ wkh_, const uint32_t* __restrict__ wkl_,
        const uint32_t* __restrict__ wvh_, const uint32_t* __restrict__ wvl_,
        const float* __restrict__ bk, const float* __restrict__ bv,
        uint32_t* __restrict__ koh, uint32_t* __restrict__ kol,
        uint32_t* __restrict__ voh, uint32_t* __restrict__ vol)
{
    constexpr int BM = 128, BN = 128;
    constexpr int FM = 4, FN = 4, LA = 2, LB = 2;
    const int K = DD, K2 = DD / 2, N = DD;
    const int z = blockIdx.z;

    const uint32_t* wh = z ? wvh_ : wkh_;
    const uint32_t* wl = z ? wvl_ : wkl_;
    const float*  bias = z ? bv : bk;

    extern __shared__ uint32_t usmem[];
    uint32_t* sAh = usmem;
    uint32_t* sAl = sAh + 2 * BM * SKS;
    uint32_t* sBh = sAl + 2 * BM * SKS;
    uint32_t* sBl = sBh + 2 * BN * SKS;

    const int tid  = threadIdx.x;
    const int lane = tid & 31;
    const int warp = tid >> 5;
    const int g = lane >> 2, t = lane & 3;
    const int mW = (warp & 1) * (BM / 2);
    const int nW = (warp >> 1) * (BN / 4);
    const int rowBase = blockIdx.y * BM;
    const int colBase = blockIdx.x * BN;

    const uint32_t sAh_u = (uint32_t)__cvta_generic_to_shared(sAh);
    const uint32_t sAl_u = (uint32_t)__cvta_generic_to_shared(sAl);
    const uint32_t sBh_u = (uint32_t)__cvta_generic_to_shared(sBh);
    const uint32_t sBl_u = (uint32_t)__cvta_generic_to_shared(sBl);

    const uint32_t aOff = (uint32_t)(((mW + (lane & 15)) * SKS + (lane >> 4) * 4) * 4);
    const uint32_t bOff = (uint32_t)(((nW + (lane >> 3) * 8 + (lane & 7)) * SKS) * 4);

    const int lr = tid >> 2;
    const int lc = (tid & 3) * 4;
    const uint32_t* Agh = pah + (size_t)(rowBase + lr) * K2 + (lc >> 1);
    const uint32_t* Agl = pal + (size_t)(rowBase + lr) * K2 + (lc >> 1);
    const uint32_t* Wgh = wh + (size_t)(colBase + lr) * K2 + (lc >> 1);
    const uint32_t* Wgl = wl + (size_t)(colBase + lr) * K2 + (lc >> 1);

    float acc[FM][FN][4];
    #pragma unroll
    for (int i = 0; i < FM; i++)
        #pragma unroll
        for (int j = 0; j < FN; j++)
            #pragma unroll
            for (int c = 0; c < 4; c++) acc[i][j][c] = 0.f;

    uint2 rah[LA], ral[LA], rwh[LB], rwl[LB];

    auto loadTile = [&](int tt) {
        #pragma unroll
        for (int i = 0; i < LA; i++) {
            rah[i] = *(const uint2*)(Agh + (size_t)i * 64 * K2 + tt * 8);
            ral[i] = *(const uint2*)(Agl + (size_t)i * 64 * K2 + tt * 8);
        }
        #pragma unroll
        for (int i = 0; i < LB; i++) {
            rwh[i] = *(const uint2*)(Wgh + (size_t)i * 64 * K2 + tt * 8);
            rwl[i] = *(const uint2*)(Wgl + (size_t)i * 64 * K2 + tt * 8);
        }
    };
    auto stage = [&](int buf) {
        #pragma unroll
        for (int i = 0; i < LA; i++) {
            int ofs = buf * BM * SKS + (lr + 64 * i) * SKS + (lc >> 1);
            *(uint2*)(sAh + ofs) = rah[i];
            *(uint2*)(sAl + ofs) = ral[i];
        }
        #pragma unroll
        for (int i = 0; i < LB; i++) {
            int ofs = buf * BN * SKS + (lr + 64 * i) * SKS + (lc >> 1);
            *(uint2*)(sBh + ofs) = rwh[i];
            *(uint2*)(sBl + ofs) = rwl[i];
        }
    };
    auto compute = [&](int buf) {
        uint32_t ah[FM][4], al[FM][4];
        uint32_t bh0[4], bh1[4], bl0[4], bl1[4];
        const uint32_t aH = sAh_u + (uint32_t)(buf * BM * SKS * 4) + aOff;
        const uint32_t aL = sAl_u + (uint32_t)(buf * BM * SKS * 4) + aOff;
        #pragma unroll
        for (int mf = 0; mf < FM; mf++) {
            ldsm4(ah[mf], aH + mf * (16 * SKS * 4));
            ldsm4(al[mf], aL + mf * (16 * SKS * 4));
        }
        const uint32_t bH = sBh_u + (uint32_t)(buf * BN * SKS * 4) + bOff;
        const uint32_t bL = sBl_u + (uint32_t)(buf * BN * SKS * 4) + bOff;
        ldsm4(bh0, bH); ldsm4(bh1, bH + 16);
        ldsm4(bl0, bL); ldsm4(bl1, bL + 16);
        #pragma unroll
        for (int mf = 0; mf < FM; mf++)
            #pragma unroll
            for (int nf = 0; nf < FN; nf++) {
                mma_bf16(acc[mf][nf], ah[mf], bh0[nf], bh1[nf]);
                mma_bf16(acc[mf][nf], ah[mf], bl0[nf], bl1[nf]);
                mma_bf16(acc[mf][nf], al[mf], bh0[nf], bh1[nf]);
            }
    };

    loadTile(0);
    stage(0);
    __syncthreads();
    const int nT = K / 16;
    int buf = 0;
    for (int tt = 1; tt < nT; tt++) {
        loadTile(tt);
        compute(buf);
        stage(buf ^ 1);
        __syncthreads();
        buf ^= 1;
    }
    compute(buf);

    if (z == 0) {
        // K epilogue: packed bf16 hi/lo along d
        #pragma unroll
        for (int mf = 0; mf < FM; mf++) {
            int row0 = rowBase + mW + mf * 16 + g;
            #pragma unroll
            for (int nf = 0; nf < FN; nf++) {
                int col = colBase + nW + nf * 8 + 2 * t;
                float2 bb = *(const float2*)(bias + col);
                uint32_t h0, l0, h1, l1;
                split2(make_float2(acc[mf][nf][0] + bb.x, acc[mf][nf][1] + bb.y), h0, l0);
                split2(make_float2(acc[mf][nf][2] + bb.x, acc[mf][nf][3] + bb.y), h1, l1);
                size_t i0 = (size_t)row0 * (N >> 1) + (col >> 1);
                size_t i1 = (size_t)(row0 + 8) * (N >> 1) + (col >> 1);
                koh[i0] = h0; kol[i0] = l0;
                koh[i1] = h1; kol[i1] = l1;
            }
        }
    } else {
        // V epilogue: transposed packed hi/lo via smem restage
        float* smf = (float*)usmem;     // [BM][68]
        #pragma unroll
        for (int p = 0; p < 2; p++) {
            __syncthreads();
            #pragma unroll
            for (int mf = 0; mf < FM; mf++) {
                int r0 = mW + mf * 16 + g;
                #pragma unroll
                for (int nf = 0; nf < FN; nf++) {
                    int col = nW + nf * 8 + 2 * t;
                    if ((col >> 6) == p) {
                        int ch = col & 63;
                        float2 bb = *(const float2*)(bias + colBase + col);
                        smf[r0 * 68 + ch]           = acc[mf][nf][0] + bb.x;
                        smf[r0 * 68 + ch + 1]       = acc[mf][nf][1] + bb.y;
                        smf[(r0 + 8) * 68 + ch]     = acc[mf][nf][2] + bb.x;
                        smf[(r0 + 8) * 68 + ch + 1] = acc[mf][nf][3] + bb.y;
                    }
                }
            }
            __syncthreads();
            const int bq = tid & 3;
            const int d  = tid >> 2;
            const int dg = colBase + p * 64 + d;
            uint32_t hbuf[16], lbuf[16];
            #pragma unroll
            for (int j = 0; j < 16; j++) {
                float v0 = smf[(8 * j + bq) * 68 + d];
                float v1 = smf[(8 * j + 4 + bq) * 68 + d];
                split2(make_float2(v0, v1), hbuf[j], lbuf[j]);
            }
            size_t base = ((size_t)bq * DD + dg) * LKH + (rowBase >> 3);
            #pragma unroll
            for (int i = 0; i < 4; i++) {
                *(uint4*)(voh + base + 4 * i) = make_uint4(hbuf[4*i], hbuf[4*i+1], hbuf[4*i+2], hbuf[4*i+3]);
                *(uint4*)(vol + base + 4 * i) = make_uint4(lbuf[4*i], lbuf[4*i+1], lbuf[4*i+2], lbuf[4*i+3]);
            }
        }
    }
}

#define SMEM_G128 (16 * SKS * (128 + 128))
#define SMEM_G64  (16 * SKS * (64 + 64))

// ------------------------- MMA banded attention (512 threads) --------------
// Register double-buffered K/V global loads to hide L2 latency.
#define SSW 968
#define PSTR 484
#define SMEM_ATTN ((2 * 16 * PSTR + 2 * 16 * SSW + 16 + 1024) * 4)

__device__ __forceinline__ int band_start(int qi) { return (qi >= 409) ? 3268 : qi * 8; }
__device__ __forceinline__ int band_wd(int qi)    { return (qi >= 409) ? 828  : 827; }

__global__ __launch_bounds__(512) void attn_mma(
        const uint32_t* __restrict__ qph,
        const uint32_t* __restrict__ qpl,
        const uint32_t* __restrict__ kh,
        const uint32_t* __restrict__ kl,
        const uint32_t* __restrict__ vth,
        const uint32_t* __restrict__ vtl,
        float* __restrict__ ctx,
        float* __restrict__ aw)
{
    extern __shared__ uint32_t sm[];
    uint32_t* sPh = sm;                         // [16][PSTR]
    uint32_t* sPl = sPh + 16 * PSTR;
    float*    sS  = (float*)(sPl + 16 * PSTR);  // [16][SSW]
    float*    aws = sS + 16 * SSW;              // [16][SSW]
    float*    sInv = aws + 16 * SSW;            // [16]
    float*    red  = sInv + 16;                 // [8][32][4]

    const int qi0 = blockIdx.x * 16;
    const int b   = blockIdx.y;
    const int tid = threadIdx.x;
    const int lane = tid & 31;
    const int warp = tid >> 5;
    const int g = lane >> 2, t = lane & 3;

    const uint32_t sPh_u = (uint32_t)__cvta_generic_to_shared(sPh);
    const uint32_t sPl_u = (uint32_t)__cvta_generic_to_shared(sPl);

    const int ustart = band_start(qi0);
    const int uend   = band_start(qi0 + 15) + band_wd(qi0 + 15);
    const int uW     = uend - ustart;
    const int ngroups = (uW + 7) >> 3;
    const int KPAD    = ((uW + 15) >> 4) << 4;
    const int nchunks = KPAD >> 4;

    const uint32_t pRowOff = (uint32_t)(((lane & 15) * PSTR + (lane >> 4) * 4) * 4);

    for (int h = 0; h < HH; h++) {
        // ---- Q fragments direct from packed global ----
        uint32_t qah[4][4], qal[4][4];
        {
            const uint32_t* q0h = qph + ((size_t)(qi0 + g) * BB + b) * (DD / 2) + h * 32;
            const uint32_t* q8h = qph + ((size_t)(qi0 + g + 8) * BB + b) * (DD / 2) + h * 32;
            const uint32_t* q0l = qpl + ((size_t)(qi0 + g) * BB + b) * (DD / 2) + h * 32;
            const uint32_t* q8l = qpl + ((size_t)(qi0 + g + 8) * BB + b) * (DD / 2) + h * 32;
            #pragma unroll
            for (int ks = 0; ks < 4; ks++) {
                qah[ks][0] = q0h[ks * 8 + t];
                qah[ks][1] = q8h[ks * 8 + t];
                qah[ks][2] = q0h[ks * 8 + t + 4];
                qah[ks][3] = q8h[ks * 8 + t + 4];
                qal[ks][0] = q0l[ks * 8 + t];
                qal[ks][1] = q8l[ks * 8 + t];
                qal[ks][2] = q0l[ks * 8 + t + 4];
                qal[ks][3] = q8l[ks * 8 + t + 4];
            }
        }

        // ---- scores: register double-buffered K loads ----
        {
            auto loadK = [&](int grp, uint32_t kb[4][4]) {
                int key = ustart + grp * 8 + g;
                if (key > LK - 1) key = LK - 1;
                const uint32_t* krh = kh + ((size_t)key * BB + b) * (DD / 2) + h * 32;
                const uint32_t* krl = kl + ((size_t)key * BB + b) * (DD / 2) + h * 32;
                #pragma unroll
                for (int ks = 0; ks < 4; ks++) {
                    kb[ks][0] = krh[ks * 8 + t];
                    kb[ks][1] = krh[ks * 8 + t + 4];
                    kb[ks][2] = krl[ks * 8 + t];
                    kb[ks][3] = krl[ks * 8 + t + 4];
                }
            };
            int grp = warp;
            if (grp < ngroups) {
                uint32_t cur[4][4], nxt[4][4];
                loadK(grp, cur);
                while (true) {
                    int ng = grp + 16;
                    if (ng < ngroups) loadK(ng, nxt);
                    float acc[4] = {0.f, 0.f, 0.f, 0.f};
                    #pragma unroll
                    for (int ks = 0; ks < 4; ks++) {
                        mma_bf16(acc, qah[ks], cur[ks][0], cur[ks][1]);
                        mma_bf16(acc, qah[ks], cur[ks][2], cur[ks][3]);
                        mma_bf16(acc, qal[ks], cur[ks][0], cur[ks][1]);
                    }
                    *(float2*)(sS + g * SSW + grp * 8 + 2 * t)       = make_float2(acc[0], acc[1]);
                    *(float2*)(sS + (g + 8) * SSW + grp * 8 + 2 * t) = make_float2(acc[2], acc[3]);
                    if (ng >= ngroups) break;
                    #pragma unroll
                    for (int ks = 0; ks < 4; ks++) {
                        cur[ks][0] = nxt[ks][0]; cur[ks][1] = nxt[ks][1];
                        cur[ks][2] = nxt[ks][2]; cur[ks][3] = nxt[ks][3];
                    }
                    grp = ng;
                }
            }
        }
        __syncthreads();

        // ---- softmax (1 row per warp) + aws accumulate + pad + pack ----
        {
            const int r  = warp;
            const int qi = qi0 + r;
            const int j0 = band_start(qi) - ustart;
            const int W  = band_wd(qi);
            float* srow = sS + r * SSW;

            float m = -1e30f;
            for (int i = j0 + lane; i < j0 + W; i += 32) m = fmaxf(m, srow[i]);
            #pragma unroll
            for (int o = 16; o > 0; o >>= 1) m = fmaxf(m, __shfl_xor_sync(0xffffffffu, m, o));
            float sum = 0.f;
            for (int i = j0 + lane; i < j0 + W; i += 32) {
                float e = __expf(srow[i] - m);
                srow[i] = e;
                sum += e;
            }
            #pragma unroll
            for (int o = 16; o > 0; o >>= 1) sum += __shfl_xor_sync(0xffffffffu, sum, o);
            float inv = 1.0f / sum;
            if (lane == 0) sInv[r] = inv;

            float cc = inv * 0.125f;   // 1/H
            float* arow = aws + r * SSW;
            if (h == 0) {
                for (int i = j0 + lane; i < j0 + W; i += 32) arow[i] = srow[i] * cc;
            } else {
                for (int i = j0 + lane; i < j0 + W; i += 32) arow[i] += srow[i] * cc;
            }
            for (int i = lane; i < j0; i += 32) srow[i] = 0.f;
            for (int i = j0 + W + lane; i < KPAD; i += 32) srow[i] = 0.f;
            __syncwarp();

            uint32_t* prow = sPh + r * PSTR;
            uint32_t* lrow = sPl + r * PSTR;
            const int npair = KPAD >> 1;
            for (int p = lane; p < npair; p += 32) {
                uint32_t ph, pl;
                split2(*(const float2*)(srow + 2 * p), ph, pl);
                prow[p] = ph;
                lrow[p] = pl;
            }
        }
        __syncthreads();

        // ---- context: register double-buffered V loads ----
        {
            const int dimBase = h * 64 + (warp & 7) * 8;
            const int kHalf = warp >> 3;
            float cacc[4] = {0.f, 0.f, 0.f, 0.f};
            const uint32_t* vhc = vth + ((size_t)b * DD + dimBase + g) * LKH;
            const uint32_t* vlc = vtl + ((size_t)b * DD + dimBase + g) * LKH;
            const int kbase = ustart >> 1;

            int ck = kHalf;
            if (ck < nchunks) {
                uint32_t vcur[4], vnxt[4];
                {
                    int kp2 = kbase + ck * 8 + t;
                    vcur[0] = vhc[kp2]; vcur[1] = vhc[kp2 + 4];
                    vcur[2] = vlc[kp2]; vcur[3] = vlc[kp2 + 4];
                }
                while (true) {
                    int nc = ck + 2;
                    if (nc < nchunks) {
                        int kp2 = kbase + nc * 8 + t;
                        vnxt[0] = vhc[kp2]; vnxt[1] = vhc[kp2 + 4];
                        vnxt[2] = vlc[kp2]; vnxt[3] = vlc[kp2 + 4];
                    }
                    uint32_t pa[4], pl[4];
                    uint32_t ko = (uint32_t)((ck * 8) * 4);
                    ldsm4(pa, sPh_u + pRowOff + ko);
                    ldsm4(pl, sPl_u + pRowOff + ko);
                    mma_bf16(cacc, pa, vcur[0], vcur[1]);
                    mma_bf16(cacc, pa, vcur[2], vcur[3]);
                    mma_bf16(cacc, pl, vcur[0], vcur[1]);
                    if (nc >= nchunks) break;
                    vcur[0] = vnxt[0]; vcur[1] = vnxt[1];
                    vcur[2] = vnxt[2]; vcur[3] = vnxt[3];
                    ck = nc;
                }
            }
            if (warp >= 8) {
                float* rp = red + (warp - 8) * 128 + lane * 4;
                rp[0] = cacc[0]; rp[1] = cacc[1]; rp[2] = cacc[2]; rp[3] = cacc[3];
            }
            __syncthreads();
            if (warp < 8) {
                const float* rp = red + warp * 128 + lane * 4;
                cacc[0] += rp[0]; cacc[1] += rp[1]; cacc[2] += rp[2]; cacc[3] += rp[3];
                float inv0 = sInv[g];
                float inv1 = sInv[g + 8];
                *(float2*)(ctx + ((size_t)(qi0 + g) * BB + b) * DD + dimBase + 2 * t) =
                    make_float2(cacc[0] * inv0, cacc[1] * inv0);
                *(float2*)(ctx + ((size_t)(qi0 + g + 8) * BB + b) * DD + dimBase + 2 * t) =
                    make_float2(cacc[2] * inv1, cacc[3] * inv1);
            }
        }
    }
    __syncthreads();

    // ---- final attn_weights write (zeros outside band) ----
    for (int i = tid; i < 16 * 1024; i += 512) {
        int r  = i >> 10;
        int c  = (i & 1023) << 2;
        int qi = qi0 + r;
        int s0 = band_start(qi);
        int W  = band_wd(qi);
        const float* arow = aws + r * SSW;
        float4 o;
        {
            int j = c + 0, jj = j - s0;
            o.x = (jj >= 0 && jj < W) ? arow[j - ustart] : 0.f;
            j = c + 1; jj = j - s0;
            o.y = (jj >= 0 && jj < W) ? arow[j - ustart] : 0.f;
            j = c + 2; jj = j - s0;
            o.z = (jj >= 0 && jj < W) ? arow[j - ustart] : 0.f;
            j = c + 3; jj = j - s0;
            o.w = (jj >= 0 && jj < W) ? arow[j - ustart] : 0.f;
        }
        *(float4*)(aw + ((size_t)b * LQ + qi) * LK + c) = o;
    }
}

// ------------------------- launch -----------------------------------------
extern "C" void kernel_launch(void* const* d_in, const int* in_sizes, int n_in,
                              void* d_out, int out_size)
{
    const float* tgt    = (const float*)d_in[0];
    const float* memory = (const float*)d_in[1];
    const float* Wq = (const float*)d_in[2];  const float* bq = (const float*)d_in[3];
    const float* Wk = (const float*)d_in[4];  const float* bk = (const float*)d_in[5];
    const float* Wv = (const float*)d_in[6];  const float* bv = (const float*)d_in[7];
    const float* Wo = (const float*)d_in[8];  const float* bo = (const float*)d_in[9];
    const float* W1 = (const float*)d_in[10]; const float* b1 = (const float*)d_in[11];
    const float* W2 = (const float*)d_in[12]; const float* b2 = (const float*)d_in[13];
    const float* ln1w = (const float*)d_in[14]; const float* ln1b = (const float*)d_in[15];
    const float* ln2w = (const float*)d_in[16]; const float* ln2b = (const float*)d_in[17];
    const float* ln3w = (const float*)d_in[18]; const float* ln3b = (const float*)d_in[19];
    const float* ln4w = (const float*)d_in[20]; const float* ln4b = (const float*)d_in[21];

    float* out    = (float*)d_out;
    float* out_x  = out;
    float* out_aw = out + (size_t)LQ * BB * DD;

    float *t_, *ctx_, *x1_, *xn_;
    uint32_t *qh_, *ql_, *mh_, *ml_, *kh_, *kl_, *vth_, *vtl_, *ff1h_, *ff1l_;
    uint32_t *wqh_, *wql_, *wkh_, *wkl_, *wvh_, *wvl_, *woh_, *wol_, *w1h_, *w1l_, *w2h_, *w2l_;
    cudaGetSymbolAddress((void**)&t_,    g_t);
    cudaGetSymbolAddress((void**)&ctx_,  g_ctx);
    cudaGetSymbolAddress((void**)&x1_,   g_x1);
    cudaGetSymbolAddress((void**)&xn_,   g_xn);
    cudaGetSymbolAddress((void**)&qh_,   g_qh);
    cudaGetSymbolAddress((void**)&ql_,   g_ql);
    cudaGetSymbolAddress((void**)&mh_,   g_mh);
    cudaGetSymbolAddress((void**)&ml_,   g_ml);
    cudaGetSymbolAddress((void**)&kh_,   g_kh);
    cudaGetSymbolAddress((void**)&kl_,   g_kl);
    cudaGetSymbolAddress((void**)&vth_,  g_vth);
    cudaGetSymbolAddress((void**)&vtl_,  g_vtl);
    cudaGetSymbolAddress((void**)&ff1h_, g_ff1h);
    cudaGetSymbolAddress((void**)&ff1l_, g_ff1l);
    cudaGetSymbolAddress((void**)&wqh_,  g_wqh); cudaGetSymbolAddress((void**)&wql_, g_wql);
    cudaGetSymbolAddress((void**)&wkh_,  g_wkh); cudaGetSymbolAddress((void**)&wkl_, g_wkl);
    cudaGetSymbolAddress((void**)&wvh_,  g_wvh); cudaGetSymbolAddress((void**)&wvl_, g_wvl);
    cudaGetSymbolAddress((void**)&woh_,  g_woh); cudaGetSymbolAddress((void**)&wol_, g_wol);
    cudaGetSymbolAddress((void**)&w1h_,  g_w1h); cudaGetSymbolAddress((void**)&w1l_, g_w1l);
    cudaGetSymbolAddress((void**)&w2h_,  g_w2h); cudaGetSymbolAddress((void**)&w2l_, g_w2l);

    cudaFuncSetAttribute(attn_mma, cudaFuncAttributeMaxDynamicSharedMemorySize, SMEM_ATTN);
    cudaFuncSetAttribute(gemm_kv, cudaFuncAttributeMaxDynamicSharedMemorySize, SMEM_G128);
    cudaFuncSetAttribute(gemm2<128,128,0,1>, cudaFuncAttributeMaxDynamicSharedMemorySize, SMEM_G128);
    cudaFuncSetAttribute(gemm2<64,64,0,0>,   cudaFuncAttributeMaxDynamicSharedMemorySize, SMEM_G64);
    cudaFuncSetAttribute(gemm2<64,64,0,1>,   cudaFuncAttributeMaxDynamicSharedMemorySize, SMEM_G64);
    cudaFuncSetAttribute(gemm2<64,64,1,0>,   cudaFuncAttributeMaxDynamicSharedMemorySize, SMEM_G64);

    // weight pre-split + LN2-normalized memory pre-split + LN1
    split_weights<<<dim3(1024, 6), 256>>>(
        Wq, Wk, Wv, Wo, W1, W2,
        wqh_, wql_, wkh_, wkl_, wvh_, wvl_, woh_, wol_, w1h_, w1l_, w2h_, w2l_);
    prep_mem<<<(LK * BB) / 8, 256>>>(memory, ln2w, ln2b, mh_, ml_);
    ln_kernel<<<LQ * BB, 256>>>(tgt, ln1w, ln1b, t_);

    // Q projection: packed, scaled by 1/8 for attention
    gemm2<64,64,0,1><<<dim3(DD / 64, (LQ * BB) / 64), 256, SMEM_G64>>>(
        t_, nullptr, nullptr, wqh_, wql_, bq, nullptr, nullptr, qh_, ql_, 0.125f, DD, DD, 0);

    // merged K + V projections (register double-buffered, proven R12 version)
    gemm_kv<<<dim3(DD / 128, (LK * BB) / 128, 2), 256, SMEM_G128>>>(
        mh_, ml_, wkh_, wkl_, wvh_, wvl_, bk, bv, kh_, kl_, vth_, vtl_);

    // MMA banded attention (512 threads)
    attn_mma<<<dim3(LQ / 16, BB), 512, SMEM_ATTN>>>(qh_, ql_, kh_, kl_, vth_, vtl_, ctx_, out_aw);

    // output projection + residual, LN3
    gemm2<64,64,0,0><<<dim3(DD / 64, (LQ * BB) / 64), 256, SMEM_G64>>>(
        ctx_, nullptr, nullptr, woh_, wol_, bo, t_, x1_, nullptr, nullptr, 1.0f, DD, DD, 0);
    ln_kernel<<<LQ * BB, 256>>>(x1_, ln3w, ln3b, xn_);

    // FFN: FF1 writes packed relu output; FF2 consumes packed A
    gemm2<128,128,0,1><<<dim3(DFF / 128, (LQ * BB) / 128), 256, SMEM_G128>>>(
        xn_, nullptr, nullptr, w1h_, w1l_, b1, nullptr, nullptr, ff1h_, ff1l_, 1.0f, DFF, DD, 1);
    gemm2<64,64,1,0><<<dim3(DD / 64, (LQ * BB) / 64), 256, SMEM_G64>>>(
        nullptr, ff1h_, ff1l_, w2h_, w2l_, b2, xn_, x1_, nullptr, nullptr, 1.0f, DD, DFF, 0);

    // LN4 -> output x
    ln_kernel<<<LQ * BB, 256>>>(x1_, ln4w, ln4b, out_x);
}

// round 15
// speedup vs baseline: 1.6966x; 1.0054x over previous
#include <cuda_runtime.h>
#include <cuda_bf16.h>
#include <math.h>
#include <stdint.h>

// Problem constants
#define LQ   512
#define LK   4096
#define BB   4
#define DD   512
#define DFF  2048
#define HH   8
#define HD   64
#define LKH  (LK / 2)
#define LN_EPS 1e-5f

// ------------------------- scratch (device globals) -----------------------
__device__ float  g_t  [LQ * BB * DD];
__device__ float  g_ctx[LQ * BB * DD];
__device__ float  g_x1 [LQ * BB * DD];
__device__ float  g_xn [LQ * BB * DD];
__device__ uint32_t g_qh [LQ * BB * (DD / 2)];        // Q (scaled) bf16-hi packed
__device__ uint32_t g_ql [LQ * BB * (DD / 2)];
__device__ uint32_t g_mh [LK * BB * (DD / 2)];        // LN2(memory) bf16-hi packed
__device__ uint32_t g_ml [LK * BB * (DD / 2)];
__device__ uint32_t g_kh [LK * BB * (DD / 2)];        // K bf16-hi packed along d
__device__ uint32_t g_kl [LK * BB * (DD / 2)];
__device__ uint32_t g_vth[BB * DD * LKH + 64];        // V^T bf16-hi packed along k
__device__ uint32_t g_vtl[BB * DD * LKH + 64];
__device__ uint32_t g_ff1h[LQ * BB * (DFF / 2)];      // relu(ff1) bf16-hi packed
__device__ uint32_t g_ff1l[LQ * BB * (DFF / 2)];
// pre-split weights: [n][k/2] packed
__device__ uint32_t g_wqh[DD * DD / 2],  g_wql[DD * DD / 2];
__device__ uint32_t g_wkh[DD * DD / 2],  g_wkl[DD * DD / 2];
__device__ uint32_t g_wvh[DD * DD / 2],  g_wvl[DD * DD / 2];
__device__ uint32_t g_woh[DD * DD / 2],  g_wol[DD * DD / 2];
__device__ uint32_t g_w1h[DFF * DD / 2], g_w1l[DFF * DD / 2];
__device__ uint32_t g_w2h[DD * DFF / 2], g_w2l[DD * DFF / 2];

// ------------------------- reductions ------------------------------------
__device__ __forceinline__ float warpReduceSum(float v) {
    #pragma unroll
    for (int o = 16; o > 0; o >>= 1) v += __shfl_down_sync(0xffffffffu, v, o);
    return v;
}
__device__ __forceinline__ float blockReduceSum256(float v, float* shared) {
    __syncthreads();
    int lane = threadIdx.x & 31, wid = threadIdx.x >> 5;
    v = warpReduceSum(v);
    if (lane == 0) shared[wid] = v;
    __syncthreads();
    if (wid == 0) {
        float x = (lane < 8) ? shared[lane] : 0.f;
        #pragma unroll
        for (int o = 4; o > 0; o >>= 1) x += __shfl_down_sync(0xffffffffu, x, o);
        if (lane == 0) shared[0] = x;
    }
    __syncthreads();
    return shared[0];
}

// ------------------------- LayerNorm (row length 512) ---------------------
__global__ void ln_kernel(const float* __restrict__ in,
                          const float* __restrict__ w,
                          const float* __restrict__ b,
                          float* __restrict__ out)
{
    __shared__ float red[8];
    const int r = blockIdx.x;
    const float* xp = in + (size_t)r * DD;
    float* op = out + (size_t)r * DD;
    int t = threadIdx.x;

    float x0 = xp[t], x1 = xp[t + 256];
    float s = blockReduceSum256(x0 + x1, red);
    float mu = s * (1.0f / DD);
    float d0 = x0 - mu, d1 = x1 - mu;
    float ss = blockReduceSum256(d0 * d0 + d1 * d1, red);
    float rstd = rsqrtf(ss * (1.0f / DD) + LN_EPS);
    op[t]       = d0 * rstd * w[t]       + b[t];
    op[t + 256] = d1 * rstd * w[t + 256] + b[t + 256];
}

// ------------------------- bf16 / mma helpers ------------------------------
__device__ __forceinline__ uint32_t pk(__nv_bfloat16 lo, __nv_bfloat16 hi) {
    unsigned short a = __bfloat16_as_ushort(lo);
    unsigned short b = __bfloat16_as_ushort(hi);
    return (uint32_t)a | ((uint32_t)b << 16);
}
__device__ __forceinline__ void split2(float2 f, uint32_t& h, uint32_t& l) {
    __nv_bfloat16 h0 = __float2bfloat16(f.x), h1 = __float2bfloat16(f.y);
    __nv_bfloat16 l0 = __float2bfloat16(f.x - __bfloat162float(h0));
    __nv_bfloat16 l1 = __float2bfloat16(f.y - __bfloat162float(h1));
    h = pk(h0, h1); l = pk(l0, l1);
}
__device__ __forceinline__ void mma_bf16(float* d, const uint32_t* a, uint32_t b0, uint32_t b1) {
    asm volatile(
        "mma.sync.aligned.m16n8k16.row.col.f32.bf16.bf16.f32 "
        "{%0,%1,%2,%3}, {%4,%5,%6,%7}, {%8,%9}, {%0,%1,%2,%3};"
        : "+f"(d[0]), "+f"(d[1]), "+f"(d[2]), "+f"(d[3])
        : "r"(a[0]), "r"(a[1]), "r"(a[2]), "r"(a[3]), "r"(b0), "r"(b1));
}
__device__ __forceinline__ void ldsm4(uint32_t* r, uint32_t saddr) {
    asm volatile("ldmatrix.sync.aligned.m8n8.x4.shared.b16 {%0,%1,%2,%3}, [%4];"
        : "=r"(r[0]), "=r"(r[1]), "=r"(r[2]), "=r"(r[3]) : "r"(saddr));
}
__device__ __forceinline__ void ldsm2(uint32_t* r, uint32_t saddr) {
    asm volatile("ldmatrix.sync.aligned.m8n8.x2.shared.b16 {%0,%1}, [%2];"
        : "=r"(r[0]), "=r"(r[1]) : "r"(saddr));
}

// ------------------------- single weight pre-split -------------------------
__global__ void split_one(const float* __restrict__ w,
                          uint32_t* __restrict__ h,
                          uint32_t* __restrict__ l,
                          int n)
{
    for (int i = blockIdx.x * 256 + threadIdx.x; i < n; i += gridDim.x * 256) {
        uint32_t hh, ll;
        split2(*(const float2*)(w + 2 * i), hh, ll);
        h[i] = hh; l[i] = ll;
    }
}

// ------------------------- LN2 + split of memory ---------------------------
__global__ void prep_mem(const float* __restrict__ in,
                         const float* __restrict__ w,
                         const float* __restrict__ b,
                         uint32_t* __restrict__ mh,
                         uint32_t* __restrict__ ml)
{
    const int row  = blockIdx.x * 8 + (threadIdx.x >> 5);
    const int lane = threadIdx.x & 31;
    const float4* p = (const float4*)(in + (size_t)row * DD);
    float4 v[4];
    float s = 0.f, s2 = 0.f;
    #pragma unroll
    for (int i = 0; i < 4; i++) {
        v[i] = p[lane + 32 * i];
        s  += v[i].x + v[i].y + v[i].z + v[i].w;
        s2 += v[i].x * v[i].x + v[i].y * v[i].y + v[i].z * v[i].z + v[i].w * v[i].w;
    }
    #pragma unroll
    for (int o = 16; o > 0; o >>= 1) {
        s  += __shfl_xor_sync(0xffffffffu, s, o);
        s2 += __shfl_xor_sync(0xffffffffu, s2, o);
    }
    float mu   = s * (1.0f / DD);
    float rstd = rsqrtf(s2 * (1.0f / DD) - mu * mu + LN_EPS);
    #pragma unroll
    for (int i = 0; i < 4; i++) {
        int idx = lane + 32 * i;
        float4 lw = ((const float4*)w)[idx];
        float4 lb = ((const float4*)b)[idx];
        float4 nv;
        nv.x = (v[i].x - mu) * rstd * lw.x + lb.x;
        nv.y = (v[i].y - mu) * rstd * lw.y + lb.y;
        nv.z = (v[i].z - mu) * rstd * lw.z + lb.z;
        nv.w = (v[i].w - mu) * rstd * lw.w + lb.w;
        uint32_t h0, l0, h1, l1;
        split2(make_float2(nv.x, nv.y), h0, l0);
        split2(make_float2(nv.z, nv.w), h1, l1);
        *(uint2*)(mh + (size_t)row * (DD / 2) + 2 * idx) = make_uint2(h0, h1);
        *(uint2*)(ml + (size_t)row * (DD / 2) + 2 * idx) = make_uint2(l0, l1);
    }
}

// ------------------------- generic GEMM (Q/O/FF1/FF2) ----------------------
// W pre-split packed [n][K/2]. APRE: A pre-split packed [r][K/2].
// MODE 0: float out (+relu/res). MODE 1: packed bf16 hi/lo out (+relu, *oscale).
#define SKS 12

template<int BM, int BN, int APRE, int MODE>
__global__ __launch_bounds__(256, (BM == 64) ? 3 : 2) void gemm2(
        const float* __restrict__ A,
        const uint32_t* __restrict__ pah,
        const uint32_t* __restrict__ pal,
        const uint32_t* __restrict__ wh,
        const uint32_t* __restrict__ wl,
        const float* __restrict__ bias,
        const float* __restrict__ res,
        float* __restrict__ out,
        uint32_t* __restrict__ oh,
        uint32_t* __restrict__ ol,
        float oscale,
        int N, int K, int doRelu)
{
    constexpr int FM = BM / 32;
    constexpr int FN = BN / 32;
    constexpr int LA = BM / 64;
    constexpr int LB = BN / 64;

    extern __shared__ uint32_t usmem[];
    uint32_t* sAh = usmem;
    uint32_t* sAl = sAh + 2 * BM * SKS;
    uint32_t* sBh = sAl + 2 * BM * SKS;
    uint32_t* sBl = sBh + 2 * BN * SKS;

    const int tid  = threadIdx.x;
    const int lane = tid & 31;
    const int warp = tid >> 5;
    const int g = lane >> 2, t = lane & 3;
    const int mW = (warp & 1) * (BM / 2);
    const int nW = (warp >> 1) * (BN / 4);
    const int rowBase = blockIdx.y * BM;
    const int colBase = blockIdx.x * BN;

    const uint32_t sAh_u = (uint32_t)__cvta_generic_to_shared(sAh);
    const uint32_t sAl_u = (uint32_t)__cvta_generic_to_shared(sAl);
    const uint32_t sBh_u = (uint32_t)__cvta_generic_to_shared(sBh);
    const uint32_t sBl_u = (uint32_t)__cvta_generic_to_shared(sBl);

    const uint32_t aOff = (uint32_t)(((mW + (lane & 15)) * SKS + (lane >> 4) * 4) * 4);
    const uint32_t bOff = (uint32_t)(((nW + (lane >> 3) * 8 + (lane & 7)) * SKS) * 4);

    const int lr = tid >> 2;
    const int lc = (tid & 3) * 4;
    const int K2 = K >> 1;
    const float*    Agf = A   ? A   + (size_t)(rowBase + lr) * K + lc : nullptr;
    const uint32_t* Agh = pah ? pah + (size_t)(rowBase + lr) * K2 + (lc >> 1) : nullptr;
    const uint32_t* Agl = pal ? pal + (size_t)(rowBase + lr) * K2 + (lc >> 1) : nullptr;
    const uint32_t* Wgh = wh + (size_t)(colBase + lr) * K2 + (lc >> 1);
    const uint32_t* Wgl = wl + (size_t)(colBase + lr) * K2 + (lc >> 1);

    float acc[FM][FN][4];
    #pragma unroll
    for (int i = 0; i < FM; i++)
        #pragma unroll
        for (int j = 0; j < FN; j++)
            #pragma unroll
            for (int c = 0; c < 4; c++) acc[i][j][c] = 0.f;

    float4 raf[LA];
    uint2  rah[LA], ral[LA];
    uint2  rwh[LB], rwl[LB];

    auto loadTile = [&](int tt) {
        if (APRE) {
            #pragma unroll
            for (int i = 0; i < LA; i++) {
                rah[i] = *(const uint2*)(Agh + (size_t)i * 64 * K2 + tt * 8);
                ral[i] = *(const uint2*)(Agl + (size_t)i * 64 * K2 + tt * 8);
            }
        } else {
            #pragma unroll
            for (int i = 0; i < LA; i++)
                raf[i] = *(const float4*)(Agf + (size_t)i * 64 * K + tt * 16);
        }
        #pragma unroll
        for (int i = 0; i < LB; i++) {
            rwh[i] = *(const uint2*)(Wgh + (size_t)i * 64 * K2 + tt * 8);
            rwl[i] = *(const uint2*)(Wgl + (size_t)i * 64 * K2 + tt * 8);
        }
    };

    auto stage = [&](int buf) {
        #pragma unroll
        for (int i = 0; i < LA; i++) {
            int ofs = buf * BM * SKS + (lr + 64 * i) * SKS + (lc >> 1);
            if (APRE) {
                *(uint2*)(sAh + ofs) = rah[i];
                *(uint2*)(sAl + ofs) = ral[i];
            } else {
                float4 v = raf[i];
                uint32_t h0, l0, h1, l1;
                split2(make_float2(v.x, v.y), h0, l0);
                split2(make_float2(v.z, v.w), h1, l1);
                *(uint2*)(sAh + ofs) = make_uint2(h0, h1);
                *(uint2*)(sAl + ofs) = make_uint2(l0, l1);
            }
        }
        #pragma unroll
        for (int i = 0; i < LB; i++) {
            int ofs = buf * BN * SKS + (lr + 64 * i) * SKS + (lc >> 1);
            *(uint2*)(sBh + ofs) = rwh[i];
            *(uint2*)(sBl + ofs) = rwl[i];
        }
    };

    auto compute = [&](int buf) {
        uint32_t ah[FM][4], al[FM][4];
        uint32_t bh0[4], bh1[4], bl0[4], bl1[4];
        const uint32_t aH = sAh_u + (uint32_t)(buf * BM * SKS * 4) + aOff;
        const uint32_t aL = sAl_u + (uint32_t)(buf * BM * SKS * 4) + aOff;
        #pragma unroll
        for (int mf = 0; mf < FM; mf++) {
            ldsm4(ah[mf], aH + mf * (16 * SKS * 4));
            ldsm4(al[mf], aL + mf * (16 * SKS * 4));
        }
        const uint32_t bH = sBh_u + (uint32_t)(buf * BN * SKS * 4) + bOff;
        const uint32_t bL = sBl_u + (uint32_t)(buf * BN * SKS * 4) + bOff;
        if (FN == 4) {
            ldsm4(bh0, bH); ldsm4(bh1, bH + 16);
            ldsm4(bl0, bL); ldsm4(bl1, bL + 16);
        } else {
            ldsm2(bh0, bH); ldsm2(bh1, bH + 16);
            ldsm2(bl0, bL); ldsm2(bl1, bL + 16);
        }
        #pragma unroll
        for (int mf = 0; mf < FM; mf++)
            #pragma unroll
            for (int nf = 0; nf < FN; nf++) {
                mma_bf16(acc[mf][nf], ah[mf], bh0[nf], bh1[nf]);
                mma_bf16(acc[mf][nf], ah[mf], bl0[nf], bl1[nf]);
                mma_bf16(acc[mf][nf], al[mf], bh0[nf], bh1[nf]);
            }
    };

    loadTile(0);
    stage(0);
    __syncthreads();

    const int nT = K / 16;
    int buf = 0;
    for (int tt = 1; tt < nT; tt++) {
        loadTile(tt);
        compute(buf);
        stage(buf ^ 1);
        __syncthreads();
        buf ^= 1;
    }
    compute(buf);

    if (MODE == 0) {
        #pragma unroll
        for (int mf = 0; mf < FM; mf++) {
            int row0 = rowBase + mW + mf * 16 + g;
            #pragma unroll
            for (int nf = 0; nf < FN; nf++) {
                int col = colBase + nW + nf * 8 + 2 * t;
                float2 bb = *(const float2*)(bias + col);
                float2 v0, v1;
                v0.x = acc[mf][nf][0] + bb.x; v0.y = acc[mf][nf][1] + bb.y;
                v1.x = acc[mf][nf][2] + bb.x; v1.y = acc[mf][nf][3] + bb.y;
                if (doRelu) {
                    v0.x = fmaxf(v0.x, 0.f); v0.y = fmaxf(v0.y, 0.f);
                    v1.x = fmaxf(v1.x, 0.f); v1.y = fmaxf(v1.y, 0.f);
                }
                if (res) {
                    float2 r0 = *(const float2*)(res + (size_t)row0 * N + col);
                    float2 r1 = *(const float2*)(res + (size_t)(row0 + 8) * N + col);
                    v0.x += r0.x; v0.y += r0.y;
                    v1.x += r1.x; v1.y += r1.y;
                }
                *(float2*)(out + (size_t)row0 * N + col) = v0;
                *(float2*)(out + (size_t)(row0 + 8) * N + col) = v1;
            }
        }
    } else {
        #pragma unroll
        for (int mf = 0; mf < FM; mf++) {
            int row0 = rowBase + mW + mf * 16 + g;
            #pragma unroll
            for (int nf = 0; nf < FN; nf++) {
                int col = colBase + nW + nf * 8 + 2 * t;
                float2 bb = *(const float2*)(bias + col);
                float a0 = acc[mf][nf][0] + bb.x, a1 = acc[mf][nf][1] + bb.y;
                float a2 = acc[mf][nf][2] + bb.x, a3 = acc[mf][nf][3] + bb.y;
                if (doRelu) {
                    a0 = fmaxf(a0, 0.f); a1 = fmaxf(a1, 0.f);
                    a2 = fmaxf(a2, 0.f); a3 = fmaxf(a3, 0.f);
                }
                a0 *= oscale; a1 *= oscale; a2 *= oscale; a3 *= oscale;
                uint32_t h0, l0, h1, l1;
                split2(make_float2(a0, a1), h0, l0);
                split2(make_float2(a2, a3), h1, l1);
                size_t i0 = (size_t)row0 * (N >> 1) + (col >> 1);
                size_t i1 = (size_t)(row0 + 8) * (N >> 1) + (col >> 1);
                oh[i0] = h0; ol[i0] = l0;
                oh[i1] = h1; ol[i1] = l1;
            }
        }
    }
}

// ------------------------- merged K+V projection (R12 proven version) ------
// blockIdx.z = 0: K-proj (packed out). blockIdx.z = 1: V-proj (transposed out).
__global__ __launch_bounds__(256, 2) void gemm_kv(
        const uint32_t* __restrict__ pah,
        const uint32_t* __restrict__ pal,
        const uint32_t* __restrict__ wkh_, const uint32_t* __restrict__ wkl_,
        const uint32_t* __restrict__ wvh_, const uint32_t* __restrict__ wvl_,
        const float* __restrict__ bk, const float* __restrict__ bv,
        uint32_t* __restrict__ koh, uint32_t* __restrict__ kol,
        uint32_t* __restrict__ voh, uint32_t* __restrict__ vol)
{
    constexpr int BM = 128, BN = 128;
    constexpr int FM = 4, FN = 4, LA = 2, LB = 2;
    const int K = DD, K2 = DD / 2, N = DD;
    const int z = blockIdx.z;

    const uint32_t* wh = z ? wvh_ : wkh_;
    const uint32_t* wl = z ? wvl_ : wkl_;
    const float*  bias = z ? bv : bk;

    extern __shared__ uint32_t usmem[];
    uint32_t* sAh = usmem;
    uint32_t* sAl = sAh + 2 * BM * SKS;
    uint32_t* sBh = sAl + 2 * BM * SKS;
    uint32_t* sBl = sBh + 2 * BN * SKS;

    const int tid  = threadIdx.x;
    const int lane = tid & 31;
    const int warp = tid >> 5;
    const int g = lane >> 2, t = lane & 3;
    const int mW = (warp & 1) * (BM / 2);
    const int nW = (warp >> 1) * (BN / 4);
    const int rowBase = blockIdx.y * BM;
    const int colBase = blockIdx.x * BN;

    const uint32_t sAh_u = (uint32_t)__cvta_generic_to_shared(sAh);
    const uint32_t sAl_u = (uint32_t)__cvta_generic_to_shared(sAl);
    const uint32_t sBh_u = (uint32_t)__cvta_generic_to_shared(sBh);
    const uint32_t sBl_u = (uint32_t)__cvta_generic_to_shared(sBl);

    const uint32_t aOff = (uint32_t)(((mW + (lane & 15)) * SKS + (lane >> 4) * 4) * 4);
    const uint32_t bOff = (uint32_t)(((nW + (lane >> 3) * 8 + (lane & 7)) * SKS) * 4);

    const int lr = tid >> 2;
    const int lc = (tid & 3) * 4;
    const uint32_t* Agh = pah + (size_t)(rowBase + lr) * K2 + (lc >> 1);
    const uint32_t* Agl = pal + (size_t)(rowBase + lr) * K2 + (lc >> 1);
    const uint32_t* Wgh = wh + (size_t)(colBase + lr) * K2 + (lc >> 1);
    const uint32_t* Wgl = wl + (size_t)(colBase + lr) * K2 + (lc >> 1);

    float acc[FM][FN][4];
    #pragma unroll
    for (int i = 0; i < FM; i++)
        #pragma unroll
        for (int j = 0; j < FN; j++)
            #pragma unroll
            for (int c = 0; c < 4; c++) acc[i][j][c] = 0.f;

    uint2 rah[LA], ral[LA], rwh[LB], rwl[LB];

    auto loadTile = [&](int tt) {
        #pragma unroll
        for (int i = 0; i < LA; i++) {
            rah[i] = *(const uint2*)(Agh + (size_t)i * 64 * K2 + tt * 8);
            ral[i] = *(const uint2*)(Agl + (size_t)i * 64 * K2 + tt * 8);
        }
        #pragma unroll
        for (int i = 0; i < LB; i++) {
            rwh[i] = *(const uint2*)(Wgh + (size_t)i * 64 * K2 + tt * 8);
            rwl[i] = *(const uint2*)(Wgl + (size_t)i * 64 * K2 + tt * 8);
        }
    };
    auto stage = [&](int buf) {
        #pragma unroll
        for (int i = 0; i < LA; i++) {
            int ofs = buf * BM * SKS + (lr + 64 * i) * SKS + (lc >> 1);
            *(uint2*)(sAh + ofs) = rah[i];
            *(uint2*)(sAl + ofs) = ral[i];
        }
        #pragma unroll
        for (int i = 0; i < LB; i++) {
            int ofs = buf * BN * SKS + (lr + 64 * i) * SKS + (lc >> 1);
            *(uint2*)(sBh + ofs) = rwh[i];
            *(uint2*)(sBl + ofs) = rwl[i];
        }
    };
    auto compute = [&](int buf) {
        uint32_t ah[FM][4], al[FM][4];
        uint32_t bh0[4], bh1[4], bl0[4], bl1[4];
        const uint32_t aH = sAh_u + (uint32_t)(buf * BM * SKS * 4) + aOff;
        const uint32_t aL = sAl_u + (uint32_t)(buf * BM * SKS * 4) + aOff;
        #pragma unroll
        for (int mf = 0; mf < FM; mf++) {
            ldsm4(ah[mf], aH + mf * (16 * SKS * 4));
            ldsm4(al[mf], aL + mf * (16 * SKS * 4));
        }
        const uint32_t bH = sBh_u + (uint32_t)(buf * BN * SKS * 4) + bOff;
        const uint32_t bL = sBl_u + (uint32_t)(buf * BN * SKS * 4) + bOff;
        ldsm4(bh0, bH); ldsm4(bh1, bH + 16);
        ldsm4(bl0, bL); ldsm4(bl1, bL + 16);
        #pragma unroll
        for (int mf = 0; mf < FM; mf++)
            #pragma unroll
            for (int nf = 0; nf < FN; nf++) {
                mma_bf16(acc[mf][nf], ah[mf], bh0[nf], bh1[nf]);
                mma_bf16(acc[mf][nf], ah[mf], bl0[nf], bl1[nf]);
                mma_bf16(acc[mf][nf], al[mf], bh0[nf], bh1[nf]);
            }
    };

    loadTile(0);
    stage(0);
    __syncthreads();
    const int nT = K / 16;
    int buf = 0;
    for (int tt = 1; tt < nT; tt++) {
        loadTile(tt);
        compute(buf);
        stage(buf ^ 1);
        __syncthreads();
        buf ^= 1;
    }
    compute(buf);

    if (z == 0) {
        // K epilogue: packed bf16 hi/lo along d
        #pragma unroll
        for (int mf = 0; mf < FM; mf++) {
            int row0 = rowBase + mW + mf * 16 + g;
            #pragma unroll
            for (int nf = 0; nf < FN; nf++) {
                int col = colBase + nW + nf * 8 + 2 * t;
                float2 bb = *(const float2*)(bias + col);
                uint32_t h0, l0, h1, l1;
                split2(make_float2(acc[mf][nf][0] + bb.x, acc[mf][nf][1] + bb.y), h0, l0);
                split2(make_float2(acc[mf][nf][2] + bb.x, acc[mf][nf][3] + bb.y), h1, l1);
                size_t i0 = (size_t)row0 * (N >> 1) + (col >> 1);
                size_t i1 = (size_t)(row0 + 8) * (N >> 1) + (col >> 1);
                koh[i0] = h0; kol[i0] = l0;
                koh[i1] = h1; kol[i1] = l1;
            }
        }
    } else {
        // V epilogue: transposed packed hi/lo via smem restage
        float* smf = (float*)usmem;     // [BM][68]
        #pragma unroll
        for (int p = 0; p < 2; p++) {
            __syncthreads();
            #pragma unroll
            for (int mf = 0; mf < FM; mf++) {
                int r0 = mW + mf * 16 + g;
                #pragma unroll
                for (int nf = 0; nf < FN; nf++) {
                    int col = nW + nf * 8 + 2 * t;
                    if ((col >> 6) == p) {
                        int ch = col & 63;
                        float2 bb = *(const float2*)(bias + colBase + col);
                        smf[r0 * 68 + ch]           = acc[mf][nf][0] + bb.x;
                        smf[r0 * 68 + ch + 1]       = acc[mf][nf][1] + bb.y;
                        smf[(r0 + 8) * 68 + ch]     = acc[mf][nf][2] + bb.x;
                        smf[(r0 + 8) * 68 + ch + 1] = acc[mf][nf][3] + bb.y;
                    }
                }
            }
            __syncthreads();
            const int bq = tid & 3;
            const int d  = tid >> 2;
            const int dg = colBase + p * 64 + d;
            uint32_t hbuf[16], lbuf[16];
            #pragma unroll
            for (int j = 0; j < 16; j++) {
                float v0 = smf[(8 * j + bq) * 68 + d];
                float v1 = smf[(8 * j + 4 + bq) * 68 + d];
                split2(make_float2(v0, v1), hbuf[j], lbuf[j]);
            }
            size_t base = ((size_t)bq * DD + dg) * LKH + (rowBase >> 3);
            #pragma unroll
            for (int i = 0; i < 4; i++) {
                *(uint4*)(voh + base + 4 * i) = make_uint4(hbuf[4*i], hbuf[4*i+1], hbuf[4*i+2], hbuf[4*i+3]);
                *(uint4*)(vol + base + 4 * i) = make_uint4(lbuf[4*i], lbuf[4*i+1], lbuf[4*i+2], lbuf[4*i+3]);
            }
        }
    }
}

#define SMEM_G128 (16 * SKS * (128 + 128))
#define SMEM_G64  (16 * SKS * (64 + 64))

// ------------------------- MMA banded attention (512 threads) --------------
#define SSW 968
#define PSTR 484
#define SMEM_ATTN ((2 * 16 * PSTR + 2 * 16 * SSW + 16 + 1024) * 4)

__device__ __forceinline__ int band_start(int qi) { return (qi >= 409) ? 3268 : qi * 8; }
__device__ __forceinline__ int band_wd(int qi)    { return (qi >= 409) ? 828  : 827; }

__global__ __launch_bounds__(512) void attn_mma(
        const uint32_t* __restrict__ qph,
        const uint32_t* __restrict__ qpl,
        const uint32_t* __restrict__ kh,
        const uint32_t* __restrict__ kl,
        const uint32_t* __restrict__ vth,
        const uint32_t* __restrict__ vtl,
        float* __restrict__ ctx,
        float* __restrict__ aw)
{
    extern __shared__ uint32_t sm[];
    uint32_t* sPh = sm;                         // [16][PSTR]
    uint32_t* sPl = sPh + 16 * PSTR;
    float*    sS  = (float*)(sPl + 16 * PSTR);  // [16][SSW]
    float*    aws = sS + 16 * SSW;              // [16][SSW]
    float*    sInv = aws + 16 * SSW;            // [16]
    float*    red  = sInv + 16;                 // [8][32][4]

    const int qi0 = blockIdx.x * 16;
    const int b   = blockIdx.y;
    const int tid = threadIdx.x;
    const int lane = tid & 31;
    const int warp = tid >> 5;
    const int g = lane >> 2, t = lane & 3;

    const uint32_t sPh_u = (uint32_t)__cvta_generic_to_shared(sPh);
    const uint32_t sPl_u = (uint32_t)__cvta_generic_to_shared(sPl);

    const int ustart = band_start(qi0);
    const int uend   = band_start(qi0 + 15) + band_wd(qi0 + 15);
    const int uW     = uend - ustart;
    const int ngroups = (uW + 7) >> 3;
    const int KPAD    = ((uW + 15) >> 4) << 4;
    const int nchunks = KPAD >> 4;

    const uint32_t pRowOff = (uint32_t)(((lane & 15) * PSTR + (lane >> 4) * 4) * 4);

    for (int h = 0; h < HH; h++) {
        // ---- Q fragments direct from packed global ----
        uint32_t qah[4][4], qal[4][4];
        {
            const uint32_t* q0h = qph + ((size_t)(qi0 + g) * BB + b) * (DD / 2) + h * 32;
            const uint32_t* q8h = qph + ((size_t)(qi0 + g + 8) * BB + b) * (DD / 2) + h * 32;
            const uint32_t* q0l = qpl + ((size_t)(qi0 + g) * BB + b) * (DD / 2) + h * 32;
            const uint32_t* q8l = qpl + ((size_t)(qi0 + g + 8) * BB + b) * (DD / 2) + h * 32;
            #pragma unroll
            for (int ks = 0; ks < 4; ks++) {
                qah[ks][0] = q0h[ks * 8 + t];
                qah[ks][1] = q8h[ks * 8 + t];
                qah[ks][2] = q0h[ks * 8 + t + 4];
                qah[ks][3] = q8h[ks * 8 + t + 4];
                qal[ks][0] = q0l[ks * 8 + t];
                qal[ks][1] = q8l[ks * 8 + t];
                qal[ks][2] = q0l[ks * 8 + t + 4];
                qal[ks][3] = q8l[ks * 8 + t + 4];
            }
        }

        // ---- scores: register double-buffered K loads ----
        {
            auto loadK = [&](int grp, uint32_t kb[4][4]) {
                int key = ustart + grp * 8 + g;
                if (key > LK - 1) key = LK - 1;
                const uint32_t* krh = kh + ((size_t)key * BB + b) * (DD / 2) + h * 32;
                const uint32_t* krl = kl + ((size_t)key * BB + b) * (DD / 2) + h * 32;
                #pragma unroll
                for (int ks = 0; ks < 4; ks++) {
                    kb[ks][0] = krh[ks * 8 + t];
                    kb[ks][1] = krh[ks * 8 + t + 4];
                    kb[ks][2] = krl[ks * 8 + t];
                    kb[ks][3] = krl[ks * 8 + t + 4];
                }
            };
            int grp = warp;
            if (grp < ngroups) {
                uint32_t cur[4][4], nxt[4][4];
                loadK(grp, cur);
                while (true) {
                    int ng = grp + 16;
                    if (ng < ngroups) loadK(ng, nxt);
                    float acc[4] = {0.f, 0.f, 0.f, 0.f};
                    #pragma unroll
                    for (int ks = 0; ks < 4; ks++) {
                        mma_bf16(acc, qah[ks], cur[ks][0], cur[ks][1]);
                        mma_bf16(acc, qah[ks], cur[ks][2], cur[ks][3]);
                        mma_bf16(acc, qal[ks], cur[ks][0], cur[ks][1]);
                    }
                    *(float2*)(sS + g * SSW + grp * 8 + 2 * t)       = make_float2(acc[0], acc[1]);
                    *(float2*)(sS + (g + 8) * SSW + grp * 8 + 2 * t) = make_float2(acc[2], acc[3]);
                    if (ng >= ngroups) break;
                    #pragma unroll
                    for (int ks = 0; ks < 4; ks++) {
                        cur[ks][0] = nxt[ks][0]; cur[ks][1] = nxt[ks][1];
                        cur[ks][2] = nxt[ks][2]; cur[ks][3] = nxt[ks][3];
                    }
                    grp = ng;
                }
            }
        }
        __syncthreads();

        // ---- softmax (1 row per warp) + aws accumulate + pad + pack ----
        {
            const int r  = warp;
            const int qi = qi0 + r;
            const int j0 = band_start(qi) - ustart;
            const int W  = band_wd(qi);
            float* srow = sS + r * SSW;

            float m = -1e30f;
            for (int i = j0 + lane; i < j0 + W; i += 32) m = fmaxf(m, srow[i]);
            #pragma unroll
            for (int o = 16; o > 0; o >>= 1) m = fmaxf(m, __shfl_xor_sync(0xffffffffu, m, o));
            float sum = 0.f;
            for (int i = j0 + lane; i < j0 + W; i += 32) {
                float e = __expf(srow[i] - m);
                srow[i] = e;
                sum += e;
            }
            #pragma unroll
            for (int o = 16; o > 0; o >>= 1) sum += __shfl_xor_sync(0xffffffffu, sum, o);
            float inv = 1.0f / sum;
            if (lane == 0) sInv[r] = inv;

            float cc = inv * 0.125f;   // 1/H
            float* arow = aws + r * SSW;
            if (h == 0) {
                for (int i = j0 + lane; i < j0 + W; i += 32) arow[i] = srow[i] * cc;
            } else {
                for (int i = j0 + lane; i < j0 + W; i += 32) arow[i] += srow[i] * cc;
            }
            for (int i = lane; i < j0; i += 32) srow[i] = 0.f;
            for (int i = j0 + W + lane; i < KPAD; i += 32) srow[i] = 0.f;
            __syncwarp();

            uint32_t* prow = sPh + r * PSTR;
            uint32_t* lrow = sPl + r * PSTR;
            const int npair = KPAD >> 1;
            for (int p = lane; p < npair; p += 32) {
                uint32_t ph, pl;
                split2(*(const float2*)(srow + 2 * p), ph, pl);
                prow[p] = ph;
                lrow[p] = pl;
            }
        }
        __syncthreads();

        // ---- context: register double-buffered V loads ----
        {
            const int dimBase = h * 64 + (warp & 7) * 8;
            const int kHalf = warp >> 3;
            float cacc[4] = {0.f, 0.f, 0.f, 0.f};
            const uint32_t* vhc = vth + ((size_t)b * DD + dimBase + g) * LKH;
            const uint32_t* vlc = vtl + ((size_t)b * DD + dimBase + g) * LKH;
            const int kbase = ustart >> 1;

            int ck = kHalf;
            if (ck < nchunks) {
                uint32_t vcur[4], vnxt[4];
                {
                    int kp2 = kbase + ck * 8 + t;
                    vcur[0] = vhc[kp2]; vcur[1] = vhc[kp2 + 4];
                    vcur[2] = vlc[kp2]; vcur[3] = vlc[kp2 + 4];
                }
                while (true) {
                    int nc = ck + 2;
                    if (nc < nchunks) {
                        int kp2 = kbase + nc * 8 + t;
                        vnxt[0] = vhc[kp2]; vnxt[1] = vhc[kp2 + 4];
                        vnxt[2] = vlc[kp2]; vnxt[3] = vlc[kp2 + 4];
                    }
                    uint32_t pa[4], pl[4];
                    uint32_t ko = (uint32_t)((ck * 8) * 4);
                    ldsm4(pa, sPh_u + pRowOff + ko);
                    ldsm4(pl, sPl_u + pRowOff + ko);
                    mma_bf16(cacc, pa, vcur[0], vcur[1]);
                    mma_bf16(cacc, pa, vcur[2], vcur[3]);
                    mma_bf16(cacc, pl, vcur[0], vcur[1]);
                    if (nc >= nchunks) break;
                    vcur[0] = vnxt[0]; vcur[1] = vnxt[1];
                    vcur[2] = vnxt[2]; vcur[3] = vnxt[3];
                    ck = nc;
                }
            }
            if (warp >= 8) {
                float* rp = red + (warp - 8) * 128 + lane * 4;
                rp[0] = cacc[0]; rp[1] = cacc[1]; rp[2] = cacc[2]; rp[3] = cacc[3];
            }
            __syncthreads();
            if (warp < 8) {
                const float* rp = red + warp * 128 + lane * 4;
                cacc[0] += rp[0]; cacc[1] += rp[1]; cacc[2] += rp[2]; cacc[3] += rp[3];
                float inv0 = sInv[g];
                float inv1 = sInv[g + 8];
                *(float2*)(ctx + ((size_t)(qi0 + g) * BB + b) * DD + dimBase + 2 * t) =
                    make_float2(cacc[0] * inv0, cacc[1] * inv0);
                *(float2*)(ctx + ((size_t)(qi0 + g + 8) * BB + b) * DD + dimBase + 2 * t) =
                    make_float2(cacc[2] * inv1, cacc[3] * inv1);
            }
        }
    }
    __syncthreads();

    // ---- final attn_weights write (zeros outside band) ----
    for (int i = tid; i < 16 * 1024; i += 512) {
        int r  = i >> 10;
        int c  = (i & 1023) << 2;
        int qi = qi0 + r;
        int s0 = band_start(qi);
        int W  = band_wd(qi);
        const float* arow = aws + r * SSW;
        float4 o;
        {
            int j = c + 0, jj = j - s0;
            o.x = (jj >= 0 && jj < W) ? arow[j - ustart] : 0.f;
            j = c + 1; jj = j - s0;
            o.y = (jj >= 0 && jj < W) ? arow[j - ustart] : 0.f;
            j = c + 2; jj = j - s0;
            o.z = (jj >= 0 && jj < W) ? arow[j - ustart] : 0.f;
            j = c + 3; jj = j - s0;
            o.w = (jj >= 0 && jj < W) ? arow[j - ustart] : 0.f;
        }
        *(float4*)(aw + ((size_t)b * LQ + qi) * LK + c) = o;
    }
}

// ------------------------- launch -----------------------------------------
extern "C" void kernel_launch(void* const* d_in, const int* in_sizes, int n_in,
                              void* d_out, int out_size)
{
    const float* tgt    = (const float*)d_in[0];
    const float* memory = (const float*)d_in[1];
    const float* Wq = (const float*)d_in[2];  const float* bq = (const float*)d_in[3];
    const float* Wk = (const float*)d_in[4];  const float* bk = (const float*)d_in[5];
    const float* Wv = (const float*)d_in[6];  const float* bv = (const float*)d_in[7];
    const float* Wo = (const float*)d_in[8];  const float* bo = (const float*)d_in[9];
    const float* W1 = (const float*)d_in[10]; const float* b1 = (const float*)d_in[11];
    const float* W2 = (const float*)d_in[12]; const float* b2 = (const float*)d_in[13];
    const float* ln1w = (const float*)d_in[14]; const float* ln1b = (const float*)d_in[15];
    const float* ln2w = (const float*)d_in[16]; const float* ln2b = (const float*)d_in[17];
    const float* ln3w = (const float*)d_in[18]; const float* ln3b = (const float*)d_in[19];
    const float* ln4w = (const float*)d_in[20]; const float* ln4b = (const float*)d_in[21];

    float* out    = (float*)d_out;
    float* out_x  = out;
    float* out_aw = out + (size_t)LQ * BB * DD;

    float *t_, *ctx_, *x1_, *xn_;
    uint32_t *qh_, *ql_, *mh_, *ml_, *kh_, *kl_, *vth_, *vtl_, *ff1h_, *ff1l_;
    uint32_t *wqh_, *wql_, *wkh_, *wkl_, *wvh_, *wvl_, *woh_, *wol_, *w1h_, *w1l_, *w2h_, *w2l_;
    cudaGetSymbolAddress((void**)&t_,    g_t);
    cudaGetSymbolAddress((void**)&ctx_,  g_ctx);
    cudaGetSymbolAddress((void**)&x1_,   g_x1);
    cudaGetSymbolAddress((void**)&xn_,   g_xn);
    cudaGetSymbolAddress((void**)&qh_,   g_qh);
    cudaGetSymbolAddress((void**)&ql_,   g_ql);
    cudaGetSymbolAddress((void**)&mh_,   g_mh);
    cudaGetSymbolAddress((void**)&ml_,   g_ml);
    cudaGetSymbolAddress((void**)&kh_,   g_kh);
    cudaGetSymbolAddress((void**)&kl_,   g_kl);
    cudaGetSymbolAddress((void**)&vth_,  g_vth);
    cudaGetSymbolAddress((void**)&vtl_,  g_vtl);
    cudaGetSymbolAddress((void**)&ff1h_, g_ff1h);
    cudaGetSymbolAddress((void**)&ff1l_, g_ff1l);
    cudaGetSymbolAddress((void**)&wqh_,  g_wqh); cudaGetSymbolAddress((void**)&wql_, g_wql);
    cudaGetSymbolAddress((void**)&wkh_,  g_wkh); cudaGetSymbolAddress((void**)&wkl_, g_wkl);
    cudaGetSymbolAddress((void**)&wvh_,  g_wvh); cudaGetSymbolAddress((void**)&wvl_, g_wvl);
    cudaGetSymbolAddress((void**)&woh_,  g_woh); cudaGetSymbolAddress((void**)&wol_, g_wol);
    cudaGetSymbolAddress((void**)&w1h_,  g_w1h); cudaGetSymbolAddress((void**)&w1l_, g_w1l);
    cudaGetSymbolAddress((void**)&w2h_,  g_w2h); cudaGetSymbolAddress((void**)&w2l_, g_w2l);

    cudaFuncSetAttribute(attn_mma, cudaFuncAttributeMaxDynamicSharedMemorySize, SMEM_ATTN);
    cudaFuncSetAttribute(gemm_kv, cudaFuncAttributeMaxDynamicSharedMemorySize, SMEM_G128);
    cudaFuncSetAttribute(gemm2<128,128,0,1>, cudaFuncAttributeMaxDynamicSharedMemorySize, SMEM_G128);
    cudaFuncSetAttribute(gemm2<64,64,0,0>,   cudaFuncAttributeMaxDynamicSharedMemorySize, SMEM_G64);
    cudaFuncSetAttribute(gemm2<64,64,0,1>,   cudaFuncAttributeMaxDynamicSharedMemorySize, SMEM_G64);
    cudaFuncSetAttribute(gemm2<64,64,1,0>,   cudaFuncAttributeMaxDynamicSharedMemorySize, SMEM_G64);

    // ---- fork a side stream (graph-capture-safe event fork/join) ----
    cudaStream_t s1;
    cudaEvent_t evFork, evJoin;
    cudaStreamCreateWithFlags(&s1, cudaStreamNonBlocking);
    cudaEventCreateWithFlags(&evFork, cudaEventDisableTiming);
    cudaEventCreateWithFlags(&evJoin, cudaEventDisableTiming);

    cudaEventRecord(evFork, 0);
    cudaStreamWaitEvent(s1, evFork, 0);

    // --- main stream (0): K/V chain (critical path) ---
    split_one<<<512, 256>>>(Wk, wkh_, wkl_, DD * DD / 2);
    split_one<<<512, 256>>>(Wv, wvh_, wvl_, DD * DD / 2);
    prep_mem<<<(LK * BB) / 8, 256>>>(memory, ln2w, ln2b, mh_, ml_);
    gemm_kv<<<dim3(DD / 128, (LK * BB) / 128, 2), 256, SMEM_G128>>>(
        mh_, ml_, wkh_, wkl_, wvh_, wvl_, bk, bv, kh_, kl_, vth_, vtl_);

    // --- side stream: Q chain + late-needed weight splits (hidden under KV) ---
    split_one<<<512, 256, 0, s1>>>(Wq, wqh_, wql_, DD * DD / 2);
    ln_kernel<<<LQ * BB, 256, 0, s1>>>(tgt, ln1w, ln1b, t_);
    gemm2<64,64,0,1><<<dim3(DD / 64, (LQ * BB) / 64), 256, SMEM_G64, s1>>>(
        t_, nullptr, nullptr, wqh_, wql_, bq, nullptr, nullptr, qh_, ql_, 0.125f, DD, DD, 0);
    split_one<<<512, 256, 0, s1>>>(Wo, woh_, wol_, DD * DD / 2);
    split_one<<<512, 256, 0, s1>>>(W1, w1h_, w1l_, DFF * DD / 2);
    split_one<<<512, 256, 0, s1>>>(W2, w2h_, w2l_, DD * DFF / 2);
    cudaEventRecord(evJoin, s1);

    // --- join: attention needs both chains ---
    cudaStreamWaitEvent(0, evJoin, 0);

    attn_mma<<<dim3(LQ / 16, BB), 512, SMEM_ATTN>>>(qh_, ql_, kh_, kl_, vth_, vtl_, ctx_, out_aw);

    // output projection + residual, LN3
    gemm2<64,64,0,0><<<dim3(DD / 64, (LQ * BB) / 64), 256, SMEM_G64>>>(
        ctx_, nullptr, nullptr, woh_, wol_, bo, t_, x1_, nullptr, nullptr, 1.0f, DD, DD, 0);
    ln_kernel<<<LQ * BB, 256>>>(x1_, ln3w, ln3b, xn_);

    // FFN: FF1 writes packed relu output; FF2 consumes packed A
    gemm2<128,128,0,1><<<dim3(DFF / 128, (LQ * BB) / 128), 256, SMEM_G128>>>(
        xn_, nullptr, nullptr, w1h_, w1l_, b1, nullptr, nullptr, ff1h_, ff1l_, 1.0f, DFF, DD, 1);
    gemm2<64,64,1,0><<<dim3(DD / 64, (LQ * BB) / 64), 256, SMEM_G64>>>(
        nullptr, ff1h_, ff1l_, w2h_, w2l_, b2, xn_, x1_, nullptr, nullptr, 1.0f, DD, DFF, 0);

    // LN4 -> output x
    ln_kernel<<<LQ * BB, 256>>>(x1_, ln4w, ln4b, out_x);

    cudaEventDestroy(evFork);
    cudaEventDestroy(evJoin);
    cudaStreamDestroy(s1);
}